// round 2
// baseline (speedup 1.0000x reference)
#include <cuda_runtime.h>
#include <math.h>

#define BATCH 512
#define SEQT  200
#define HID   128
#define GATES 512   // 4H
#define EMB   128
#define MTOT  (BATCH*SEQT)   // 102400
#define RPB   8              // batch rows per LSTM block

// ---------------- static scratch ----------------
__device__ float g_zx_fw[(size_t)MTOT * GATES];
__device__ float g_zx_bw[(size_t)MTOT * GATES];
__device__ float g_s0f[(size_t)MTOT * HID];
__device__ float g_s0b[(size_t)MTOT * HID];
__device__ float g_s1f[(size_t)MTOT * HID];
__device__ float g_s1b[(size_t)MTOT * HID];

// ---------------- packed f32x2 helpers (sm_100a) ----------------
__device__ __forceinline__ unsigned long long ffma2(unsigned long long a,
                                                    unsigned long long b,
                                                    unsigned long long c) {
    unsigned long long d;
    asm("fma.rn.f32x2 %0, %1, %2, %3;" : "=l"(d) : "l"(a), "l"(b), "l"(c));
    return d;
}
__device__ __forceinline__ unsigned long long pack2(float x, float y) {
    unsigned long long d;
    asm("mov.b64 %0, {%1, %2};" : "=l"(d) : "f"(x), "f"(y));
    return d;
}
__device__ __forceinline__ void unpack2(unsigned long long v, float& x, float& y) {
    asm("mov.b64 {%0, %1}, %2;" : "=f"(x), "=f"(y) : "l"(v));
}

// ---------------- GEMM: C[m,n] = sum_k A[m,k]*Wm[k,n] + bias[n] ----------------
// A:[MTOT,128], Wm:[128,512], C:[MTOT,512]. Tile 128x128, BK=32, 256 thr, 8x8/thread.
// Inner product done with packed FFMA2: acc2[i][j] packs columns (2j, 2j+1).
__global__ __launch_bounds__(256) void gemm_zx(
    const float* __restrict__ A, const float* __restrict__ Wm,
    const float* __restrict__ bias, float* __restrict__ C)
{
    __shared__ __align__(16) float As[32][128];   // As[k][m]
    __shared__ __align__(16) float Bs[32][128];   // Bs[k][n]

    int tid = threadIdx.x;
    int tx = tid & 15;
    int ty = tid >> 4;
    size_t m0 = (size_t)blockIdx.y * 128;
    int n0 = blockIdx.x * 128;

    unsigned long long acc2[8][4];
    const unsigned long long z2 = 0ull;
#pragma unroll
    for (int i = 0; i < 8; i++)
#pragma unroll
        for (int j = 0; j < 4; j++) acc2[i][j] = z2;

    for (int k0 = 0; k0 < EMB; k0 += 32) {
#pragma unroll
        for (int i = 0; i < 4; i++) {
            int idx = tid + i * 256;
            int row = idx >> 3;
            int kq  = idx & 7;
            float4 v = *(const float4*)&A[(m0 + row) * EMB + k0 + kq * 4];
            As[kq*4+0][row] = v.x; As[kq*4+1][row] = v.y;
            As[kq*4+2][row] = v.z; As[kq*4+3][row] = v.w;
        }
#pragma unroll
        for (int i = 0; i < 4; i++) {
            int idx = tid + i * 256;
            int row = idx >> 5;
            int nq  = idx & 31;
            *(float4*)&Bs[row][nq*4] =
                *(const float4*)&Wm[(size_t)(k0 + row) * GATES + n0 + nq * 4];
        }
        __syncthreads();
#pragma unroll
        for (int kk = 0; kk < 32; kk++) {
            float4 a0 = *(const float4*)&As[kk][ty*8];
            float4 a1 = *(const float4*)&As[kk][ty*8+4];
            // b as native packed pairs along n
            ulonglong2 b0 = *(const ulonglong2*)&Bs[kk][tx*8];
            ulonglong2 b1 = *(const ulonglong2*)&Bs[kk][tx*8+4];
            unsigned long long bp[4] = {b0.x, b0.y, b1.x, b1.y};
            float av[8] = {a0.x,a0.y,a0.z,a0.w,a1.x,a1.y,a1.z,a1.w};
#pragma unroll
            for (int i = 0; i < 8; i++) {
                unsigned long long a2 = pack2(av[i], av[i]);
#pragma unroll
                for (int j = 0; j < 4; j++)
                    acc2[i][j] = ffma2(a2, bp[j], acc2[i][j]);
            }
        }
        __syncthreads();
    }

    float bl[8];
#pragma unroll
    for (int j = 0; j < 8; j++) bl[j] = bias[n0 + tx*8 + j];
#pragma unroll
    for (int i = 0; i < 8; i++) {
        size_t m = m0 + ty*8 + i;
        float* crow = &C[m * GATES + n0 + tx*8];
        float o[8];
#pragma unroll
        for (int j = 0; j < 4; j++) unpack2(acc2[i][j], o[2*j], o[2*j+1]);
        float4 o0, o1;
        o0.x = o[0]+bl[0]; o0.y = o[1]+bl[1]; o0.z = o[2]+bl[2]; o0.w = o[3]+bl[3];
        o1.x = o[4]+bl[4]; o1.y = o[5]+bl[5]; o1.z = o[6]+bl[6]; o1.w = o[7]+bl[7];
        ((float4*)crow)[0] = o0; ((float4*)crow)[1] = o1;
    }
}

// ---------------- LSTM recurrence ----------------
__device__ __forceinline__ float sigm(float x) { return 1.f / (1.f + __expf(-x)); }

// grid (64, 2): y = direction. 8 batch rows/block, 512 threads.
// z phase: thread n computes gate column n for 8 rows, packed as 4 f32x2 row-pairs.
__global__ __launch_bounds__(512) void lstm_dir(
    const float* __restrict__ zx_fw, const float* __restrict__ zx_bw,
    const float* __restrict__ U_fw,  const float* __restrict__ U_bw,
    float* __restrict__ out_fw, float* __restrict__ out_bw)
{
    const int dir = blockIdx.y;
    const float* __restrict__ zx = dir ? zx_bw : zx_fw;
    const float* __restrict__ U  = dir ? U_bw  : U_fw;
    float* __restrict__ out      = dir ? out_bw : out_fw;

    const int b0  = blockIdx.x * RPB;
    const int tid = threadIdx.x;

    __shared__ __align__(16) float h_s[HID][RPB];  // h_s[k][r]
    __shared__ __align__(16) float zb[RPB][GATES];

    for (int q = tid; q < HID * RPB; q += 512) ((float*)h_s)[q] = 0.f;
    float c0 = 0.f, c1 = 0.f;

    const int n  = tid;
    const int j  = tid & 127;
    const int rp = (tid >> 7) << 1;     // 0,2,4,6

    __syncthreads();

    for (int s = 0; s < SEQT; s++) {
        const int t = dir ? (SEQT - 1 - s) : s;

        // init acc from zx (pack row pairs)
        unsigned long long acc2[4];
        {
            const float* zxp = zx + ((size_t)b0 * SEQT + t) * GATES + n;
            float a[RPB];
#pragma unroll
            for (int r = 0; r < RPB; r++)
                a[r] = zxp[(size_t)r * SEQT * GATES];
#pragma unroll
            for (int p = 0; p < 4; p++) acc2[p] = pack2(a[2*p], a[2*p+1]);
        }

        const float* Up = U + n;
#pragma unroll 8
        for (int k = 0; k < HID; k++) {
            float u = Up[(size_t)k * GATES];
            unsigned long long u2 = pack2(u, u);
            ulonglong2 ha = *(const ulonglong2*)&h_s[k][0];  // rows 0-3
            ulonglong2 hb = *(const ulonglong2*)&h_s[k][4];  // rows 4-7
            acc2[0] = ffma2(ha.x, u2, acc2[0]);
            acc2[1] = ffma2(ha.y, u2, acc2[1]);
            acc2[2] = ffma2(hb.x, u2, acc2[2]);
            acc2[3] = ffma2(hb.y, u2, acc2[3]);
        }
#pragma unroll
        for (int p = 0; p < 4; p++) {
            float lo, hi;
            unpack2(acc2[p], lo, hi);
            zb[2*p][n] = lo;
            zb[2*p+1][n] = hi;
        }
        __syncthreads();

        {
            float zi = zb[rp][j], zf = zb[rp][128 + j];
            float zg = zb[rp][256 + j], zo = zb[rp][384 + j];
            float ig = sigm(zi), fg = sigm(zf), gg = tanhf(zg), og = sigm(zo);
            c0 = fg * c0 + ig * gg;
            float h = og * tanhf(c0);
            h_s[j][rp] = h;
            out[((size_t)(b0 + rp) * SEQT + t) * HID + j] = h;
        }
        {
            float zi = zb[rp+1][j], zf = zb[rp+1][128 + j];
            float zg = zb[rp+1][256 + j], zo = zb[rp+1][384 + j];
            float ig = sigm(zi), fg = sigm(zf), gg = tanhf(zg), og = sigm(zo);
            c1 = fg * c1 + ig * gg;
            float h = og * tanhf(c1);
            h_s[j][rp+1] = h;
            out[((size_t)(b0 + rp + 1) * SEQT + t) * HID + j] = h;
        }
        __syncthreads();
    }
}

// ---------------- final combine ----------------
__global__ void combine(const float* __restrict__ a, const float* __restrict__ b,
                        const float* __restrict__ c, const float* __restrict__ d,
                        float* __restrict__ out, int n4)
{
    int i = blockIdx.x * blockDim.x + threadIdx.x;
    if (i < n4) {
        float4 va = ((const float4*)a)[i];
        float4 vb = ((const float4*)b)[i];
        float4 vc = ((const float4*)c)[i];
        float4 vd = ((const float4*)d)[i];
        float4 o;
        o.x = 0.5f * (va.x + vb.x + vc.x + vd.x);
        o.y = 0.5f * (va.y + vb.y + vc.y + vd.y);
        o.z = 0.5f * (va.z + vb.z + vc.z + vd.z);
        o.w = 0.5f * (va.w + vb.w + vc.w + vd.w);
        ((float4*)out)[i] = o;
    }
}

// ---------------- launch ----------------
extern "C" void kernel_launch(void* const* d_in, const int* in_sizes, int n_in,
                              void* d_out, int out_size)
{
    const float* x = (const float*)d_in[0];
    const float* W = (const float*)d_in[1];
    const float* U = (const float*)d_in[2];
    const float* b = (const float*)d_in[3];

    float *zxf, *zxb, *s0f, *s0b, *s1f, *s1b;
    cudaGetSymbolAddress((void**)&zxf, g_zx_fw);
    cudaGetSymbolAddress((void**)&zxb, g_zx_bw);
    cudaGetSymbolAddress((void**)&s0f, g_s0f);
    cudaGetSymbolAddress((void**)&s0b, g_s0b);
    cudaGetSymbolAddress((void**)&s1f, g_s1f);
    cudaGetSymbolAddress((void**)&s1b, g_s1b);

    const size_t WSZ = (size_t)EMB * GATES;
    const float* W00 = W;           const float* W01 = W + WSZ;
    const float* W10 = W + 2*WSZ;   const float* W11 = W + 3*WSZ;
    const float* U00 = U;           const float* U01 = U + WSZ;
    const float* U10 = U + 2*WSZ;   const float* U11 = U + 3*WSZ;
    const float* b00 = b;           const float* b01 = b + GATES;
    const float* b10 = b + 2*GATES; const float* b11 = b + 3*GATES;

    dim3 gg(GATES / 128, MTOT / 128);
    dim3 gb(256);
    dim3 lg(BATCH / RPB, 2);

    gemm_zx<<<gg, gb>>>(x, W00, b00, zxf);
    gemm_zx<<<gg, gb>>>(x, W01, b01, zxb);
    lstm_dir<<<lg, 512>>>(zxf, zxb, U00, U01, s0f, s0b);

    gemm_zx<<<gg, gb>>>(s0f, W10, b10, zxf);
    gemm_zx<<<gg, gb>>>(s0b, W11, b11, zxb);
    lstm_dir<<<lg, 512>>>(zxf, zxb, U10, U11, s1f, s1b);

    int n4 = MTOT * HID / 4;
    combine<<<(n4 + 255) / 256, 256>>>(s1f, s0f, s1b, s0b, (float*)d_out, n4);
}

// round 4
// speedup vs baseline: 1.2835x; 1.2835x over previous
#include <cuda_runtime.h>
#include <math.h>
#include <stdint.h>

#define BATCH 512
#define SEQT  200
#define HID   128
#define GATES 512   // 4H
#define EMB   128
#define MTOT  (BATCH*SEQT)   // 102400
#define RPB   8

// ---------------- static scratch ----------------
__device__ float g_zx_fw[(size_t)MTOT * GATES];
__device__ float g_zx_bw[(size_t)MTOT * GATES];
__device__ float g_s0f[(size_t)MTOT * HID];
__device__ float g_s0b[(size_t)MTOT * HID];
__device__ float g_s1f[(size_t)MTOT * HID];
__device__ float g_s1b[(size_t)MTOT * HID];
__device__ float g_Wt[4 * GATES * EMB];   // transposed + tf32-rounded W: [4][n=512][k=128]

// ---------------- helpers ----------------
__device__ __forceinline__ float to_tf32(float x) {
    uint32_t y;
    asm("cvt.rna.tf32.f32 %0, %1;" : "=r"(y) : "f"(x));
    return __uint_as_float(y);
}

__device__ __forceinline__ void mma_tf32(float* d, const uint32_t* a, const uint32_t* b) {
    asm volatile(
        "mma.sync.aligned.m16n8k8.row.col.f32.tf32.tf32.f32 "
        "{%0,%1,%2,%3}, {%4,%5,%6,%7}, {%8,%9}, {%0,%1,%2,%3};"
        : "+f"(d[0]), "+f"(d[1]), "+f"(d[2]), "+f"(d[3])
        : "r"(a[0]), "r"(a[1]), "r"(a[2]), "r"(a[3]), "r"(b[0]), "r"(b[1]));
}

// ---------------- tensor-core GEMM: C[m,n] = A[m,k] @ Wt[n,k]^T + bias[n] ----------------
// A:[MTOT,128] f32, Wt:[512,128] tf32-rounded. Tile M=128,N=128; Kc=64 x 2 passes.
// 256 threads = 8 warps in 2(m) x 4(n); warp tile 64x32; m16n8k8 tf32.
#define KC 64
#define LDA 68   // padded stride (68 % 32 == 4 -> conflict-free frag loads)
#define GSMEM (2 * 128 * LDA * 4)

__global__ __launch_bounds__(256) void gemm_tc(
    const float* __restrict__ A, const float* __restrict__ Wt,
    const float* __restrict__ bias, float* __restrict__ C)
{
    extern __shared__ __align__(16) char smem[];
    float (*As)[LDA] = (float(*)[LDA])smem;                       // [128][68]
    float (*Bs)[LDA] = (float(*)[LDA])(smem + 128 * LDA * 4);     // [128][68]

    const int tid = threadIdx.x;
    const int wid = tid >> 5;
    const int lane = tid & 31;
    const int wm = wid & 1;        // 0..1
    const int wn = wid >> 1;       // 0..3
    const int g = lane >> 2;       // groupID 0..7
    const int tig = lane & 3;      // thread-in-group

    const size_t m0 = (size_t)blockIdx.y * 128;
    const int n0 = blockIdx.x * 128;

    float acc[4][4][4];
#pragma unroll
    for (int mt = 0; mt < 4; mt++)
#pragma unroll
        for (int nt = 0; nt < 4; nt++)
#pragma unroll
            for (int q = 0; q < 4; q++) acc[mt][nt][q] = 0.f;

#pragma unroll
    for (int kt = 0; kt < 2; kt++) {
        // stage A (cvt to tf32) and B tiles: 128 rows x 64 cols each
#pragma unroll
        for (int i = 0; i < 8; i++) {
            int idx = tid + i * 256;       // 0..2047 float4 slots
            int row = idx >> 4;            // 0..127
            int c4  = idx & 15;            // 0..15
            float4 va = *(const float4*)&A[(m0 + row) * EMB + kt * KC + c4 * 4];
            va.x = to_tf32(va.x); va.y = to_tf32(va.y);
            va.z = to_tf32(va.z); va.w = to_tf32(va.w);
            *(float4*)&As[row][c4 * 4] = va;
            float4 vb = *(const float4*)&Wt[(size_t)(n0 + row) * EMB + kt * KC + c4 * 4];
            *(float4*)&Bs[row][c4 * 4] = vb;
        }
        __syncthreads();

#pragma unroll
        for (int k8 = 0; k8 < 8; k8++) {
            const int kb = k8 * 8;
            uint32_t af[4][4];
#pragma unroll
            for (int mt = 0; mt < 4; mt++) {
                int r = wm * 64 + mt * 16 + g;
                af[mt][0] = __float_as_uint(As[r][kb + tig]);
                af[mt][1] = __float_as_uint(As[r + 8][kb + tig]);
                af[mt][2] = __float_as_uint(As[r][kb + tig + 4]);
                af[mt][3] = __float_as_uint(As[r + 8][kb + tig + 4]);
            }
            uint32_t bf[4][2];
#pragma unroll
            for (int nt = 0; nt < 4; nt++) {
                int n = wn * 32 + nt * 8 + g;
                bf[nt][0] = __float_as_uint(Bs[n][kb + tig]);
                bf[nt][1] = __float_as_uint(Bs[n][kb + tig + 4]);
            }
#pragma unroll
            for (int mt = 0; mt < 4; mt++)
#pragma unroll
                for (int nt = 0; nt < 4; nt++)
                    mma_tf32(acc[mt][nt], af[mt], bf[nt]);
        }
        __syncthreads();
    }

    // epilogue: thread owns rows (g, g+8), cols 2*tig, 2*tig+1 of each 16x8 tile
#pragma unroll
    for (int nt = 0; nt < 4; nt++) {
        int col = n0 + wn * 32 + nt * 8 + 2 * tig;
        float b0 = bias[col], b1 = bias[col + 1];
#pragma unroll
        for (int mt = 0; mt < 4; mt++) {
            size_t row = m0 + wm * 64 + mt * 16 + g;
            float2 o0 = { acc[mt][nt][0] + b0, acc[mt][nt][1] + b1 };
            float2 o1 = { acc[mt][nt][2] + b0, acc[mt][nt][3] + b1 };
            *(float2*)&C[row * GATES + col] = o0;
            *(float2*)&C[(row + 8) * GATES + col] = o1;
        }
    }
}

// ---------------- W transpose + tf32 rounding: W[4][128][512] -> Wt[4][512][128] ----------------
__global__ void transpose_w(const float* __restrict__ W, float* __restrict__ Wt)
{
    int idx = blockIdx.x * blockDim.x + threadIdx.x;
    if (idx < 4 * EMB * GATES) {
        int gsel = idx >> 16;
        int r = (idx >> 9) & 127;   // k
        int c = idx & 511;          // n
        Wt[(size_t)gsel * GATES * EMB + (size_t)c * EMB + r] = to_tf32(W[idx]);
    }
}

// ---------------- LSTM recurrence (scalar fp32, round-1 proven) ----------------
__device__ __forceinline__ float sigm(float x) { return 1.f / (1.f + __expf(-x)); }

__global__ __launch_bounds__(512) void lstm_dir(
    const float* __restrict__ zx_fw, const float* __restrict__ zx_bw,
    const float* __restrict__ U_fw,  const float* __restrict__ U_bw,
    float* __restrict__ out_fw, float* __restrict__ out_bw)
{
    const int dir = blockIdx.y;
    const float* __restrict__ zx = dir ? zx_bw : zx_fw;
    const float* __restrict__ U  = dir ? U_bw  : U_fw;
    float* __restrict__ out      = dir ? out_bw : out_fw;

    const int b0  = blockIdx.x * RPB;
    const int tid = threadIdx.x;

    __shared__ __align__(16) float h_s[HID][RPB];
    __shared__ __align__(16) float zb[RPB][GATES];

    for (int q = tid; q < HID * RPB; q += 512) ((float*)h_s)[q] = 0.f;
    float c0 = 0.f, c1 = 0.f;

    const int n  = tid;
    const int j  = tid & 127;
    const int rp = (tid >> 7) << 1;

    __syncthreads();

    for (int s = 0; s < SEQT; s++) {
        const int t = dir ? (SEQT - 1 - s) : s;

        float acc[RPB];
        const float* zxp = zx + ((size_t)b0 * SEQT + t) * GATES + n;
#pragma unroll
        for (int r = 0; r < RPB; r++)
            acc[r] = zxp[(size_t)r * SEQT * GATES];

        const float* Up = U + n;
#pragma unroll 8
        for (int k = 0; k < HID; k++) {
            float u = Up[(size_t)k * GATES];
            float4 ha = *(const float4*)&h_s[k][0];
            float4 hb = *(const float4*)&h_s[k][4];
            acc[0] = fmaf(ha.x, u, acc[0]);
            acc[1] = fmaf(ha.y, u, acc[1]);
            acc[2] = fmaf(ha.z, u, acc[2]);
            acc[3] = fmaf(ha.w, u, acc[3]);
            acc[4] = fmaf(hb.x, u, acc[4]);
            acc[5] = fmaf(hb.y, u, acc[5]);
            acc[6] = fmaf(hb.z, u, acc[6]);
            acc[7] = fmaf(hb.w, u, acc[7]);
        }
#pragma unroll
        for (int r = 0; r < RPB; r++) zb[r][n] = acc[r];
        __syncthreads();

        {
            float zi = zb[rp][j], zf = zb[rp][128 + j];
            float zg = zb[rp][256 + j], zo = zb[rp][384 + j];
            float ig = sigm(zi), fg = sigm(zf), gg = tanhf(zg), og = sigm(zo);
            c0 = fg * c0 + ig * gg;
            float h = og * tanhf(c0);
            h_s[j][rp] = h;
            out[((size_t)(b0 + rp) * SEQT + t) * HID + j] = h;
        }
        {
            float zi = zb[rp+1][j], zf = zb[rp+1][128 + j];
            float zg = zb[rp+1][256 + j], zo = zb[rp+1][384 + j];
            float ig = sigm(zi), fg = sigm(zf), gg = tanhf(zg), og = sigm(zo);
            c1 = fg * c1 + ig * gg;
            float h = og * tanhf(c1);
            h_s[j][rp+1] = h;
            out[((size_t)(b0 + rp + 1) * SEQT + t) * HID + j] = h;
        }
        __syncthreads();
    }
}

// ---------------- final combine ----------------
__global__ void combine(const float* __restrict__ a, const float* __restrict__ b,
                        const float* __restrict__ c, const float* __restrict__ d,
                        float* __restrict__ out, int n4)
{
    int i = blockIdx.x * blockDim.x + threadIdx.x;
    if (i < n4) {
        float4 va = ((const float4*)a)[i];
        float4 vb = ((const float4*)b)[i];
        float4 vc = ((const float4*)c)[i];
        float4 vd = ((const float4*)d)[i];
        float4 o;
        o.x = 0.5f * (va.x + vb.x + vc.x + vd.x);
        o.y = 0.5f * (va.y + vb.y + vc.y + vd.y);
        o.z = 0.5f * (va.z + vb.z + vc.z + vd.z);
        o.w = 0.5f * (va.w + vb.w + vc.w + vd.w);
        ((float4*)out)[i] = o;
    }
}

// ---------------- launch ----------------
extern "C" void kernel_launch(void* const* d_in, const int* in_sizes, int n_in,
                              void* d_out, int out_size)
{
    const float* x = (const float*)d_in[0];
    const float* W = (const float*)d_in[1];
    const float* U = (const float*)d_in[2];
    const float* b = (const float*)d_in[3];

    float *zxf, *zxb, *s0f, *s0b, *s1f, *s1b, *Wt;
    cudaGetSymbolAddress((void**)&zxf, g_zx_fw);
    cudaGetSymbolAddress((void**)&zxb, g_zx_bw);
    cudaGetSymbolAddress((void**)&s0f, g_s0f);
    cudaGetSymbolAddress((void**)&s0b, g_s0b);
    cudaGetSymbolAddress((void**)&s1f, g_s1f);
    cudaGetSymbolAddress((void**)&s1b, g_s1b);
    cudaGetSymbolAddress((void**)&Wt, g_Wt);

    cudaFuncSetAttribute(gemm_tc, cudaFuncAttributeMaxDynamicSharedMemorySize, GSMEM);

    const size_t WSZ = (size_t)EMB * GATES;
    const float* U00 = U;           const float* U01 = U + WSZ;
    const float* U10 = U + 2*WSZ;   const float* U11 = U + 3*WSZ;
    const float* b00 = b;           const float* b01 = b + GATES;
    const float* b10 = b + 2*GATES; const float* b11 = b + 3*GATES;
    float* Wt00 = Wt;           float* Wt01 = Wt + WSZ;
    float* Wt10 = Wt + 2*WSZ;   float* Wt11 = Wt + 3*WSZ;

    transpose_w<<<(4 * EMB * GATES + 255) / 256, 256>>>(W, Wt);

    dim3 gg(GATES / 128, MTOT / 128);   // (4, 800)
    dim3 lg(BATCH / RPB, 2);            // (64, 2)

    gemm_tc<<<gg, 256, GSMEM>>>(x, Wt00, b00, zxf);
    gemm_tc<<<gg, 256, GSMEM>>>(x, Wt01, b01, zxb);
    lstm_dir<<<lg, 512>>>(zxf, zxb, U00, U01, s0f, s0b);

    gemm_tc<<<gg, 256, GSMEM>>>(s0f, Wt10, b10, zxf);
    gemm_tc<<<gg, 256, GSMEM>>>(s0b, Wt11, b11, zxb);
    lstm_dir<<<lg, 512>>>(zxf, zxb, U10, U11, s1f, s1b);

    int n4 = MTOT * HID / 4;
    combine<<<(n4 + 255) / 256, 256>>>(s1f, s0f, s1b, s0b, (float*)d_out, n4);
}

// round 5
// speedup vs baseline: 1.6680x; 1.2996x over previous
#include <cuda_runtime.h>
#include <math.h>
#include <stdint.h>

#define BATCH 512
#define SEQT  200
#define HID   128
#define GATES 512   // 4H
#define EMB   128
#define MTOT  (BATCH*SEQT)   // 102400

// ---------------- static scratch ----------------
__device__ float g_zx_fw[(size_t)MTOT * GATES];
__device__ float g_zx_bw[(size_t)MTOT * GATES];
__device__ float g_s0f[(size_t)MTOT * HID];
__device__ float g_s0b[(size_t)MTOT * HID];
__device__ float g_s1f[(size_t)MTOT * HID];
__device__ float g_s1b[(size_t)MTOT * HID];
__device__ float g_Wt[4 * GATES * EMB];     // transposed + tf32-rounded W: [4][n=512][k=128]
__device__ float g_Ufrag[4 * 64 * 16 * 32 * 2];  // mma-fragment-swizzled U (tf32), 1MB

// ---------------- helpers ----------------
__device__ __forceinline__ float to_tf32(float x) {
    uint32_t y;
    asm("cvt.rna.tf32.f32 %0, %1;" : "=r"(y) : "f"(x));
    return __uint_as_float(y);
}

__device__ __forceinline__ void mma_tf32(float* d, const uint32_t* a, const uint32_t* b) {
    asm volatile(
        "mma.sync.aligned.m16n8k8.row.col.f32.tf32.tf32.f32 "
        "{%0,%1,%2,%3}, {%4,%5,%6,%7}, {%8,%9}, {%0,%1,%2,%3};"
        : "+f"(d[0]), "+f"(d[1]), "+f"(d[2]), "+f"(d[3])
        : "r"(a[0]), "r"(a[1]), "r"(a[2]), "r"(a[3]), "r"(b[0]), "r"(b[1]));
}

// ---------------- tensor-core GEMM: C[m,n] = A[m,k] @ Wt[n,k]^T + bias[n] ----------------
#define KC 64
#define LDA 68
#define GSMEM (2 * 128 * LDA * 4)

__global__ __launch_bounds__(256) void gemm_tc(
    const float* __restrict__ A, const float* __restrict__ Wt,
    const float* __restrict__ bias, float* __restrict__ C)
{
    extern __shared__ __align__(16) char smem[];
    float (*As)[LDA] = (float(*)[LDA])smem;
    float (*Bs)[LDA] = (float(*)[LDA])(smem + 128 * LDA * 4);

    const int tid = threadIdx.x;
    const int wid = tid >> 5;
    const int lane = tid & 31;
    const int wm = wid & 1;
    const int wn = wid >> 1;
    const int g = lane >> 2;
    const int tig = lane & 3;

    const size_t m0 = (size_t)blockIdx.y * 128;
    const int n0 = blockIdx.x * 128;

    float acc[4][4][4];
#pragma unroll
    for (int mt = 0; mt < 4; mt++)
#pragma unroll
        for (int nt = 0; nt < 4; nt++)
#pragma unroll
            for (int q = 0; q < 4; q++) acc[mt][nt][q] = 0.f;

#pragma unroll
    for (int kt = 0; kt < 2; kt++) {
#pragma unroll
        for (int i = 0; i < 8; i++) {
            int idx = tid + i * 256;
            int row = idx >> 4;
            int c4  = idx & 15;
            float4 va = *(const float4*)&A[(m0 + row) * EMB + kt * KC + c4 * 4];
            va.x = to_tf32(va.x); va.y = to_tf32(va.y);
            va.z = to_tf32(va.z); va.w = to_tf32(va.w);
            *(float4*)&As[row][c4 * 4] = va;
            float4 vb = *(const float4*)&Wt[(size_t)(n0 + row) * EMB + kt * KC + c4 * 4];
            *(float4*)&Bs[row][c4 * 4] = vb;
        }
        __syncthreads();

#pragma unroll
        for (int k8 = 0; k8 < 8; k8++) {
            const int kb = k8 * 8;
            uint32_t af[4][4];
#pragma unroll
            for (int mt = 0; mt < 4; mt++) {
                int r = wm * 64 + mt * 16 + g;
                af[mt][0] = __float_as_uint(As[r][kb + tig]);
                af[mt][1] = __float_as_uint(As[r + 8][kb + tig]);
                af[mt][2] = __float_as_uint(As[r][kb + tig + 4]);
                af[mt][3] = __float_as_uint(As[r + 8][kb + tig + 4]);
            }
            uint32_t bf[4][2];
#pragma unroll
            for (int nt = 0; nt < 4; nt++) {
                int n = wn * 32 + nt * 8 + g;
                bf[nt][0] = __float_as_uint(Bs[n][kb + tig]);
                bf[nt][1] = __float_as_uint(Bs[n][kb + tig + 4]);
            }
#pragma unroll
            for (int mt = 0; mt < 4; mt++)
#pragma unroll
                for (int nt = 0; nt < 4; nt++)
                    mma_tf32(acc[mt][nt], af[mt], bf[nt]);
        }
        __syncthreads();
    }

#pragma unroll
    for (int nt = 0; nt < 4; nt++) {
        int col = n0 + wn * 32 + nt * 8 + 2 * tig;
        float b0 = bias[col], b1 = bias[col + 1];
#pragma unroll
        for (int mt = 0; mt < 4; mt++) {
            size_t row = m0 + wm * 64 + mt * 16 + g;
            float2 o0 = { acc[mt][nt][0] + b0, acc[mt][nt][1] + b1 };
            float2 o1 = { acc[mt][nt][2] + b0, acc[mt][nt][3] + b1 };
            *(float2*)&C[row * GATES + col] = o0;
            *(float2*)&C[(row + 8) * GATES + col] = o1;
        }
    }
}

// ---------------- W transpose + tf32 rounding ----------------
__global__ void transpose_w(const float* __restrict__ W, float* __restrict__ Wt)
{
    int idx = blockIdx.x * blockDim.x + threadIdx.x;
    if (idx < 4 * EMB * GATES) {
        int gsel = idx >> 16;
        int r = (idx >> 9) & 127;
        int c = idx & 511;
        Wt[(size_t)gsel * GATES * EMB + (size_t)c * EMB + r] = to_tf32(W[idx]);
    }
}

// ---------------- U fragment pre-swizzle ----------------
// UF[u][ntg 64][kt 16][lane 32][p 2] = tf32(U_u[kt*8 + (lane&3) + 4p][ntg*8 + (lane>>2)])
__global__ void build_ufrag(const float* __restrict__ U, float* __restrict__ UF)
{
    int idx = blockIdx.x * blockDim.x + threadIdx.x;
    if (idx < 4 * 64 * 16 * 32 * 2) {
        int p    = idx & 1;
        int lane = (idx >> 1) & 31;
        int kt   = (idx >> 6) & 15;
        int ntg  = (idx >> 10) & 63;
        int u    = idx >> 16;
        int tig = lane & 3, gg = lane >> 2;
        int k = kt * 8 + tig + 4 * p;
        int n = ntg * 8 + gg;
        UF[idx] = to_tf32(U[(size_t)u * (EMB * GATES) + (size_t)k * GATES + n]);
    }
}

// ---------------- tensor-core LSTM recurrence ----------------
__device__ __forceinline__ float sigm(float x) { return 1.f / (1.f + __expf(-x)); }

// grid (32, 2), block 512 (16 warps). 16 batch rows per block.
// Per step: z[16,512] = h[16,128]@U + zx, via m16n8k8 tf32; warp w owns cols [32w,32w+32).
__global__ __launch_bounds__(512) void lstm_tc(
    const float* __restrict__ zx_fw, const float* __restrict__ zx_bw,
    const float* __restrict__ uf_fw, const float* __restrict__ uf_bw,
    float* __restrict__ out_fw, float* __restrict__ out_bw)
{
    const int dir = blockIdx.y;
    const float* __restrict__ zx = dir ? zx_bw : zx_fw;
    const float2* __restrict__ uf = (const float2*)(dir ? uf_bw : uf_fw);
    float* __restrict__ out = dir ? out_bw : out_fw;

    const int b0  = blockIdx.x * 16;
    const int tid = threadIdx.x;
    const int wid = tid >> 5;
    const int lane = tid & 31;
    const int g = lane >> 2;
    const int tig = lane & 3;
    const int ntg0 = wid * 4;

    __shared__ __align__(16) float h_s[16][132];   // tf32-rounded h, padded
    __shared__ __align__(16) float zb[16][520];    // z = h@U exchange, padded

    for (int q = tid; q < 16 * 132; q += 512) ((float*)h_s)[q] = 0.f;
    float c[4] = {0.f, 0.f, 0.f, 0.f};

    const int j  = tid & 127;
    const int r0 = tid >> 7;      // 0..3 -> rows r0, r0+4, r0+8, r0+12

    __syncthreads();

    for (int s = 0; s < SEQT; s++) {
        const int t = dir ? (SEQT - 1 - s) : s;

        // ---- mma phase: z = h @ U ----
        float acc[4][4];
#pragma unroll
        for (int nt = 0; nt < 4; nt++)
#pragma unroll
            for (int q = 0; q < 4; q++) acc[nt][q] = 0.f;

#pragma unroll
        for (int kt = 0; kt < 16; kt++) {
            const int kb = kt * 8;
            uint32_t a[4];
            a[0] = __float_as_uint(h_s[g][kb + tig]);
            a[1] = __float_as_uint(h_s[g + 8][kb + tig]);
            a[2] = __float_as_uint(h_s[g][kb + tig + 4]);
            a[3] = __float_as_uint(h_s[g + 8][kb + tig + 4]);
#pragma unroll
            for (int nt = 0; nt < 4; nt++) {
                float2 bv = uf[((ntg0 + nt) * 16 + kt) * 32 + lane];
                uint32_t b[2] = { __float_as_uint(bv.x), __float_as_uint(bv.y) };
                mma_tf32(acc[nt], a, b);
            }
        }
#pragma unroll
        for (int nt = 0; nt < 4; nt++) {
            int col = wid * 32 + nt * 8 + 2 * tig;
            *(float2*)&zb[g][col]     = make_float2(acc[nt][0], acc[nt][1]);
            *(float2*)&zb[g + 8][col] = make_float2(acc[nt][2], acc[nt][3]);
        }
        __syncthreads();

        // ---- gate phase: 4 (row, j) cells per thread ----
#pragma unroll
        for (int rr = 0; rr < 4; rr++) {
            const int r = r0 + rr * 4;
            const float* zp = zx + ((size_t)(b0 + r) * SEQT + t) * GATES;
            float zi = zb[r][j]       + zp[j];
            float zf = zb[r][128 + j] + zp[128 + j];
            float zg = zb[r][256 + j] + zp[256 + j];
            float zo = zb[r][384 + j] + zp[384 + j];
            float ig = sigm(zi), fg = sigm(zf), gg2 = tanhf(zg), og = sigm(zo);
            c[rr] = fg * c[rr] + ig * gg2;
            float h = og * tanhf(c[rr]);
            h_s[r][j] = to_tf32(h);
            out[((size_t)(b0 + r) * SEQT + t) * HID + j] = h;
        }
        __syncthreads();
    }
}

// ---------------- final combine ----------------
__global__ void combine(const float* __restrict__ a, const float* __restrict__ b,
                        const float* __restrict__ c, const float* __restrict__ d,
                        float* __restrict__ out, int n4)
{
    int i = blockIdx.x * blockDim.x + threadIdx.x;
    if (i < n4) {
        float4 va = ((const float4*)a)[i];
        float4 vb = ((const float4*)b)[i];
        float4 vc = ((const float4*)c)[i];
        float4 vd = ((const float4*)d)[i];
        float4 o;
        o.x = 0.5f * (va.x + vb.x + vc.x + vd.x);
        o.y = 0.5f * (va.y + vb.y + vc.y + vd.y);
        o.z = 0.5f * (va.z + vb.z + vc.z + vd.z);
        o.w = 0.5f * (va.w + vb.w + vc.w + vd.w);
        ((float4*)out)[i] = o;
    }
}

// ---------------- launch ----------------
extern "C" void kernel_launch(void* const* d_in, const int* in_sizes, int n_in,
                              void* d_out, int out_size)
{
    const float* x = (const float*)d_in[0];
    const float* W = (const float*)d_in[1];
    const float* U = (const float*)d_in[2];
    const float* b = (const float*)d_in[3];

    float *zxf, *zxb, *s0f, *s0b, *s1f, *s1b, *Wt, *UF;
    cudaGetSymbolAddress((void**)&zxf, g_zx_fw);
    cudaGetSymbolAddress((void**)&zxb, g_zx_bw);
    cudaGetSymbolAddress((void**)&s0f, g_s0f);
    cudaGetSymbolAddress((void**)&s0b, g_s0b);
    cudaGetSymbolAddress((void**)&s1f, g_s1f);
    cudaGetSymbolAddress((void**)&s1b, g_s1b);
    cudaGetSymbolAddress((void**)&Wt, g_Wt);
    cudaGetSymbolAddress((void**)&UF, g_Ufrag);

    cudaFuncSetAttribute(gemm_tc, cudaFuncAttributeMaxDynamicSharedMemorySize, GSMEM);

    const size_t WSZ = (size_t)EMB * GATES;   // 65536
    const float* b00 = b;           const float* b01 = b + GATES;
    const float* b10 = b + 2*GATES; const float* b11 = b + 3*GATES;
    float* Wt00 = Wt;           float* Wt01 = Wt + WSZ;
    float* Wt10 = Wt + 2*WSZ;   float* Wt11 = Wt + 3*WSZ;
    float* UF00 = UF;           float* UF01 = UF + WSZ;   // u index = layer*2 + dir
    float* UF10 = UF + 2*WSZ;   float* UF11 = UF + 3*WSZ;

    transpose_w<<<(4 * EMB * GATES + 255) / 256, 256>>>(W, Wt);
    build_ufrag<<<(4 * EMB * GATES + 255) / 256, 256>>>(U, UF);

    dim3 gg(GATES / 128, MTOT / 128);   // (4, 800)
    dim3 lg(BATCH / 16, 2);             // (32, 2)

    gemm_tc<<<gg, 256, GSMEM>>>(x, Wt00, b00, zxf);
    gemm_tc<<<gg, 256, GSMEM>>>(x, Wt01, b01, zxb);
    lstm_tc<<<lg, 512>>>(zxf, zxb, UF00, UF01, s0f, s0b);

    gemm_tc<<<gg, 256, GSMEM>>>(s0f, Wt10, b10, zxf);
    gemm_tc<<<gg, 256, GSMEM>>>(s0b, Wt11, b11, zxb);
    lstm_tc<<<lg, 512>>>(zxf, zxb, UF10, UF11, s1f, s1b);

    int n4 = MTOT * HID / 4;
    combine<<<(n4 + 255) / 256, 256>>>(s1f, s0f, s1b, s0b, (float*)d_out, n4);
}

// round 6
// speedup vs baseline: 1.8627x; 1.1167x over previous
#include <cuda_runtime.h>
#include <math.h>
#include <stdint.h>

#define BATCH 512
#define SEQT  200
#define HID   128
#define GATES 512   // 4H
#define EMB   128
#define MTOT  (BATCH*SEQT)   // 102400

// ---------------- static scratch ----------------
__device__ float g_zx_fw[(size_t)MTOT * GATES];
__device__ float g_zx_bw[(size_t)MTOT * GATES];
__device__ float g_s0f[(size_t)MTOT * HID];
__device__ float g_s0b[(size_t)MTOT * HID];
__device__ float g_s1f[(size_t)MTOT * HID];
__device__ float g_s1b[(size_t)MTOT * HID];
__device__ float g_Wt[4 * GATES * EMB];          // transposed + tf32-rounded W
__device__ float g_Ufrag[4 * 64 * 8 * 32 * 4];   // U fragments, kt-pair interleaved (LDG.128)

// ---------------- helpers ----------------
__device__ __forceinline__ float to_tf32(float x) {
    uint32_t y;
    asm("cvt.rna.tf32.f32 %0, %1;" : "=r"(y) : "f"(x));
    return __uint_as_float(y);
}
__device__ __forceinline__ float rcp_(float x) {
    float y; asm("rcp.approx.f32 %0, %1;" : "=f"(y) : "f"(x)); return y;
}
__device__ __forceinline__ float ex2_(float x) {
    float y; asm("ex2.approx.f32 %0, %1;" : "=f"(y) : "f"(x)); return y;
}
__device__ __forceinline__ float sigm(float x) {
    return rcp_(1.f + ex2_(-1.4426950408889634f * x));
}
__device__ __forceinline__ float tanh_(float x) {
    return 1.f - 2.f * rcp_(1.f + ex2_(2.8853900817779268f * x));
}

__device__ __forceinline__ void mma_tf32(float* d, const uint32_t* a, uint32_t b0, uint32_t b1) {
    asm volatile(
        "mma.sync.aligned.m16n8k8.row.col.f32.tf32.tf32.f32 "
        "{%0,%1,%2,%3}, {%4,%5,%6,%7}, {%8,%9}, {%0,%1,%2,%3};"
        : "+f"(d[0]), "+f"(d[1]), "+f"(d[2]), "+f"(d[3])
        : "r"(a[0]), "r"(a[1]), "r"(a[2]), "r"(a[3]), "r"(b0), "r"(b1));
}

// ---------------- tensor-core GEMM (unchanged from round 4) ----------------
#define KC 64
#define LDA 68
#define GSMEM (2 * 128 * LDA * 4)

__global__ __launch_bounds__(256) void gemm_tc(
    const float* __restrict__ A, const float* __restrict__ Wt,
    const float* __restrict__ bias, float* __restrict__ C)
{
    extern __shared__ __align__(16) char smem[];
    float (*As)[LDA] = (float(*)[LDA])smem;
    float (*Bs)[LDA] = (float(*)[LDA])(smem + 128 * LDA * 4);

    const int tid = threadIdx.x;
    const int wid = tid >> 5;
    const int lane = tid & 31;
    const int wm = wid & 1;
    const int wn = wid >> 1;
    const int g = lane >> 2;
    const int tig = lane & 3;

    const size_t m0 = (size_t)blockIdx.y * 128;
    const int n0 = blockIdx.x * 128;

    float acc[4][4][4];
#pragma unroll
    for (int mt = 0; mt < 4; mt++)
#pragma unroll
        for (int nt = 0; nt < 4; nt++)
#pragma unroll
            for (int q = 0; q < 4; q++) acc[mt][nt][q] = 0.f;

#pragma unroll
    for (int kt = 0; kt < 2; kt++) {
#pragma unroll
        for (int i = 0; i < 8; i++) {
            int idx = tid + i * 256;
            int row = idx >> 4;
            int c4  = idx & 15;
            float4 va = *(const float4*)&A[(m0 + row) * EMB + kt * KC + c4 * 4];
            va.x = to_tf32(va.x); va.y = to_tf32(va.y);
            va.z = to_tf32(va.z); va.w = to_tf32(va.w);
            *(float4*)&As[row][c4 * 4] = va;
            float4 vb = *(const float4*)&Wt[(size_t)(n0 + row) * EMB + kt * KC + c4 * 4];
            *(float4*)&Bs[row][c4 * 4] = vb;
        }
        __syncthreads();

#pragma unroll
        for (int k8 = 0; k8 < 8; k8++) {
            const int kb = k8 * 8;
            uint32_t af[4][4];
#pragma unroll
            for (int mt = 0; mt < 4; mt++) {
                int r = wm * 64 + mt * 16 + g;
                af[mt][0] = __float_as_uint(As[r][kb + tig]);
                af[mt][1] = __float_as_uint(As[r + 8][kb + tig]);
                af[mt][2] = __float_as_uint(As[r][kb + tig + 4]);
                af[mt][3] = __float_as_uint(As[r + 8][kb + tig + 4]);
            }
#pragma unroll
            for (int nt = 0; nt < 4; nt++) {
                int n = wn * 32 + nt * 8 + g;
                uint32_t b0 = __float_as_uint(Bs[n][kb + tig]);
                uint32_t b1 = __float_as_uint(Bs[n][kb + tig + 4]);
#pragma unroll
                for (int mt = 0; mt < 4; mt++)
                    mma_tf32(acc[mt][nt], af[mt], b0, b1);
            }
        }
        __syncthreads();
    }

#pragma unroll
    for (int nt = 0; nt < 4; nt++) {
        int col = n0 + wn * 32 + nt * 8 + 2 * tig;
        float b0 = bias[col], b1 = bias[col + 1];
#pragma unroll
        for (int mt = 0; mt < 4; mt++) {
            size_t row = m0 + wm * 64 + mt * 16 + g;
            float2 o0 = { acc[mt][nt][0] + b0, acc[mt][nt][1] + b1 };
            float2 o1 = { acc[mt][nt][2] + b0, acc[mt][nt][3] + b1 };
            *(float2*)&C[row * GATES + col] = o0;
            *(float2*)&C[(row + 8) * GATES + col] = o1;
        }
    }
}

// ---------------- W transpose + tf32 rounding ----------------
__global__ void transpose_w(const float* __restrict__ W, float* __restrict__ Wt)
{
    int idx = blockIdx.x * blockDim.x + threadIdx.x;
    if (idx < 4 * EMB * GATES) {
        int gsel = idx >> 16;
        int r = (idx >> 9) & 127;
        int c = idx & 511;
        Wt[(size_t)gsel * GATES * EMB + (size_t)c * EMB + r] = to_tf32(W[idx]);
    }
}

// ---------------- U fragment pre-swizzle (kt-pair interleaved for LDG.128) ----------------
// UF[u][ntg 64][kt2 8][lane 32][q 4]; kt = 2*kt2 + (q>>1); p = q&1;
// value = tf32(U_u[kt*8 + (lane&3) + 4p][ntg*8 + (lane>>2)])
__global__ void build_ufrag(const float* __restrict__ U, float* __restrict__ UF)
{
    int idx = blockIdx.x * blockDim.x + threadIdx.x;
    if (idx < 4 * 64 * 8 * 32 * 4) {
        int q    = idx & 3;
        int lane = (idx >> 2) & 31;
        int kt2  = (idx >> 7) & 7;
        int ntg  = (idx >> 10) & 63;
        int u    = idx >> 16;
        int tig = lane & 3, gg = lane >> 2;
        int kt = kt2 * 2 + (q >> 1);
        int p  = q & 1;
        int k = kt * 8 + tig + 4 * p;
        int n = ntg * 8 + gg;
        UF[idx] = to_tf32(U[(size_t)u * (EMB * GATES) + (size_t)k * GATES + n]);
    }
}

// ---------------- fused tensor-core LSTM recurrence ----------------
// grid (32, 2), block 512 (16 warps), 16 batch rows/block.
// Warp w owns gate quadruple columns {8w..8w+8} x {i,f,g,o}: acc[nt] = gate nt.
// Gates computed in registers; h ping-pong in smem; ONE barrier per step.
__global__ __launch_bounds__(512) void lstm_tc(
    const float* __restrict__ zx_fw, const float* __restrict__ zx_bw,
    const float* __restrict__ uf_fw, const float* __restrict__ uf_bw,
    float* __restrict__ out_fw, float* __restrict__ out_bw)
{
    const int dir = blockIdx.y;
    const float* __restrict__ zx = dir ? zx_bw : zx_fw;
    const float* __restrict__ uf = dir ? uf_bw : uf_fw;
    float* __restrict__ out = dir ? out_bw : out_fw;

    const int b0  = blockIdx.x * 16;
    const int tid = threadIdx.x;
    const int w   = tid >> 5;
    const int lane = tid & 31;
    const int g = lane >> 2;
    const int tig = lane & 3;
    const int col0 = 8 * w + 2 * tig;     // hidden-unit column pair base

    __shared__ __align__(16) float h_s[2][16][132];   // ping-pong tf32 h

    for (int q2 = tid; q2 < 2 * 16 * 132; q2 += 512) ((float*)h_s)[q2] = 0.f;
    float c[4] = {0.f, 0.f, 0.f, 0.f};

    // per-nt U fragment base pointers (ntg = w + 16*nt)
    const float4* ufp[4];
#pragma unroll
    for (int nt = 0; nt < 4; nt++)
        ufp[nt] = (const float4*)uf + (size_t)(w + 16 * nt) * 8 * 32 + lane;

    const float* zr0 = zx + ((size_t)(b0 + g) * SEQT) * GATES + col0;
    const float* zr1 = zx + ((size_t)(b0 + g + 8) * SEQT) * GATES + col0;
    float* or0 = out + ((size_t)(b0 + g) * SEQT) * HID + col0;
    float* or1 = out + ((size_t)(b0 + g + 8) * SEQT) * HID + col0;

    __syncthreads();

    for (int s = 0; s < SEQT; s++) {
        const int t = dir ? (SEQT - 1 - s) : s;
        const int rb = s & 1;
        const int wb = rb ^ 1;

        // prefetch zx for this step (overlaps with mma below)
        float2 zv0[4], zv1[4];
#pragma unroll
        for (int nt = 0; nt < 4; nt++) {
            zv0[nt] = *(const float2*)&zr0[(size_t)t * GATES + 128 * nt];
            zv1[nt] = *(const float2*)&zr1[(size_t)t * GATES + 128 * nt];
        }

        // ---- mma phase: z = h @ U ----
        float acc[4][4];
#pragma unroll
        for (int nt = 0; nt < 4; nt++)
#pragma unroll
            for (int q = 0; q < 4; q++) acc[nt][q] = 0.f;

#pragma unroll
        for (int kt2 = 0; kt2 < 8; kt2++) {
            const int kbe = kt2 * 16;       // even kt cols
            uint32_t ae[4], ao[4];
            ae[0] = __float_as_uint(h_s[rb][g][kbe + tig]);
            ae[1] = __float_as_uint(h_s[rb][g + 8][kbe + tig]);
            ae[2] = __float_as_uint(h_s[rb][g][kbe + tig + 4]);
            ae[3] = __float_as_uint(h_s[rb][g + 8][kbe + tig + 4]);
            ao[0] = __float_as_uint(h_s[rb][g][kbe + 8 + tig]);
            ao[1] = __float_as_uint(h_s[rb][g + 8][kbe + 8 + tig]);
            ao[2] = __float_as_uint(h_s[rb][g][kbe + 8 + tig + 4]);
            ao[3] = __float_as_uint(h_s[rb][g + 8][kbe + 8 + tig + 4]);
#pragma unroll
            for (int nt = 0; nt < 4; nt++) {
                float4 bv = ufp[nt][kt2 * 32];
                mma_tf32(acc[nt], ae, __float_as_uint(bv.x), __float_as_uint(bv.y));
                mma_tf32(acc[nt], ao, __float_as_uint(bv.z), __float_as_uint(bv.w));
            }
        }

        // ---- gate phase (registers only) ----
        // acc[0]=i, acc[1]=f, acc[2]=g, acc[3]=o; q:0,1 = row g cols 0,1; 2,3 = row g+8
        float h00, h01, h10, h11;
        {
            float ig = sigm(acc[0][0] + zv0[0].x), fg = sigm(acc[1][0] + zv0[1].x);
            float gg = tanh_(acc[2][0] + zv0[2].x), og = sigm(acc[3][0] + zv0[3].x);
            c[0] = fg * c[0] + ig * gg;  h00 = og * tanh_(c[0]);
        }
        {
            float ig = sigm(acc[0][1] + zv0[0].y), fg = sigm(acc[1][1] + zv0[1].y);
            float gg = tanh_(acc[2][1] + zv0[2].y), og = sigm(acc[3][1] + zv0[3].y);
            c[1] = fg * c[1] + ig * gg;  h01 = og * tanh_(c[1]);
        }
        {
            float ig = sigm(acc[0][2] + zv1[0].x), fg = sigm(acc[1][2] + zv1[1].x);
            float gg = tanh_(acc[2][2] + zv1[2].x), og = sigm(acc[3][2] + zv1[3].x);
            c[2] = fg * c[2] + ig * gg;  h10 = og * tanh_(c[2]);
        }
        {
            float ig = sigm(acc[0][3] + zv1[0].y), fg = sigm(acc[1][3] + zv1[1].y);
            float gg = tanh_(acc[2][3] + zv1[2].y), og = sigm(acc[3][3] + zv1[3].y);
            c[3] = fg * c[3] + ig * gg;  h11 = og * tanh_(c[3]);
        }

        // write tf32 h to next-step buffer; fp32 h to gmem
        *(float2*)&h_s[wb][g][col0]     = make_float2(to_tf32(h00), to_tf32(h01));
        *(float2*)&h_s[wb][g + 8][col0] = make_float2(to_tf32(h10), to_tf32(h11));
        *(float2*)&or0[(size_t)t * HID] = make_float2(h00, h01);
        *(float2*)&or1[(size_t)t * HID] = make_float2(h10, h11);

        __syncthreads();
    }
}

// ---------------- final combine ----------------
__global__ void combine(const float* __restrict__ a, const float* __restrict__ b,
                        const float* __restrict__ c, const float* __restrict__ d,
                        float* __restrict__ out, int n4)
{
    int i = blockIdx.x * blockDim.x + threadIdx.x;
    if (i < n4) {
        float4 va = ((const float4*)a)[i];
        float4 vb = ((const float4*)b)[i];
        float4 vc = ((const float4*)c)[i];
        float4 vd = ((const float4*)d)[i];
        float4 o;
        o.x = 0.5f * (va.x + vb.x + vc.x + vd.x);
        o.y = 0.5f * (va.y + vb.y + vc.y + vd.y);
        o.z = 0.5f * (va.z + vb.z + vc.z + vd.z);
        o.w = 0.5f * (va.w + vb.w + vc.w + vd.w);
        ((float4*)out)[i] = o;
    }
}

// ---------------- launch ----------------
extern "C" void kernel_launch(void* const* d_in, const int* in_sizes, int n_in,
                              void* d_out, int out_size)
{
    const float* x = (const float*)d_in[0];
    const float* W = (const float*)d_in[1];
    const float* U = (const float*)d_in[2];
    const float* b = (const float*)d_in[3];

    float *zxf, *zxb, *s0f, *s0b, *s1f, *s1b, *Wt, *UF;
    cudaGetSymbolAddress((void**)&zxf, g_zx_fw);
    cudaGetSymbolAddress((void**)&zxb, g_zx_bw);
    cudaGetSymbolAddress((void**)&s0f, g_s0f);
    cudaGetSymbolAddress((void**)&s0b, g_s0b);
    cudaGetSymbolAddress((void**)&s1f, g_s1f);
    cudaGetSymbolAddress((void**)&s1b, g_s1b);
    cudaGetSymbolAddress((void**)&Wt, g_Wt);
    cudaGetSymbolAddress((void**)&UF, g_Ufrag);

    cudaFuncSetAttribute(gemm_tc, cudaFuncAttributeMaxDynamicSharedMemorySize, GSMEM);

    const size_t WSZ = (size_t)EMB * GATES;   // 65536
    const float* b00 = b;           const float* b01 = b + GATES;
    const float* b10 = b + 2*GATES; const float* b11 = b + 3*GATES;
    float* Wt00 = Wt;           float* Wt01 = Wt + WSZ;
    float* Wt10 = Wt + 2*WSZ;   float* Wt11 = Wt + 3*WSZ;
    float* UF00 = UF;           float* UF01 = UF + WSZ;
    float* UF10 = UF + 2*WSZ;   float* UF11 = UF + 3*WSZ;

    transpose_w<<<(4 * EMB * GATES + 255) / 256, 256>>>(W, Wt);
    build_ufrag<<<(4 * EMB * GATES + 255) / 256, 256>>>(U, UF);

    dim3 gg(GATES / 128, MTOT / 128);   // (4, 800)
    dim3 lg(BATCH / 16, 2);             // (32, 2)

    gemm_tc<<<gg, 256, GSMEM>>>(x, Wt00, b00, zxf);
    gemm_tc<<<gg, 256, GSMEM>>>(x, Wt01, b01, zxb);
    lstm_tc<<<lg, 512>>>(zxf, zxb, UF00, UF01, s0f, s0b);

    gemm_tc<<<gg, 256, GSMEM>>>(s0f, Wt10, b10, zxf);
    gemm_tc<<<gg, 256, GSMEM>>>(s0b, Wt11, b11, zxb);
    lstm_tc<<<lg, 512>>>(zxf, zxb, UF10, UF11, s1f, s1b);

    int n4 = MTOT * HID / 4;
    combine<<<(n4 + 255) / 256, 256>>>(s1f, s0f, s1b, s0b, (float*)d_out, n4);
}

// round 8
// speedup vs baseline: 2.3094x; 1.2398x over previous
#include <cuda_runtime.h>
#include <math.h>
#include <stdint.h>

#define BATCH 512
#define SEQT  200
#define HID   128
#define GATES 512   // 4H
#define EMB   128
#define MTOT  (BATCH*SEQT)   // 102400

// ---------------- static scratch ----------------
__device__ float g_zx_fw[(size_t)MTOT * GATES];
__device__ float g_zx_bw[(size_t)MTOT * GATES];
__device__ float g_s0f[(size_t)MTOT * HID];
__device__ float g_s0b[(size_t)MTOT * HID];
__device__ float g_s1f[(size_t)MTOT * HID];
__device__ float g_s1b[(size_t)MTOT * HID];
__device__ float g_Wt[4 * GATES * EMB];          // transposed + tf32-rounded W
__device__ float g_Ufrag[4 * 64 * 8 * 32 * 4];   // U fragments, kt-pair interleaved (LDG.128)

// ---------------- helpers ----------------
__device__ __forceinline__ float to_tf32(float x) {
    uint32_t y;
    asm("cvt.rna.tf32.f32 %0, %1;" : "=r"(y) : "f"(x));
    return __uint_as_float(y);
}
__device__ __forceinline__ float rcp_(float x) {
    float y; asm("rcp.approx.f32 %0, %1;" : "=f"(y) : "f"(x)); return y;
}
__device__ __forceinline__ float ex2_(float x) {
    float y; asm("ex2.approx.f32 %0, %1;" : "=f"(y) : "f"(x)); return y;
}
__device__ __forceinline__ float sigm(float x) {
    return rcp_(1.f + ex2_(-1.4426950408889634f * x));
}
__device__ __forceinline__ float tanh_(float x) {
    return 1.f - 2.f * rcp_(1.f + ex2_(2.8853900817779268f * x));
}

__device__ __forceinline__ void mma_tf32(float* d, const uint32_t* a, uint32_t b0, uint32_t b1) {
    asm volatile(
        "mma.sync.aligned.m16n8k8.row.col.f32.tf32.tf32.f32 "
        "{%0,%1,%2,%3}, {%4,%5,%6,%7}, {%8,%9}, {%0,%1,%2,%3};"
        : "+f"(d[0]), "+f"(d[1]), "+f"(d[2]), "+f"(d[3])
        : "r"(a[0]), "r"(a[1]), "r"(a[2]), "r"(a[3]), "r"(b0), "r"(b1));
}

// ---------------- tensor-core GEMM (unchanged) ----------------
#define KC 64
#define LDA 68
#define GSMEM (2 * 128 * LDA * 4)

__global__ __launch_bounds__(256) void gemm_tc(
    const float* __restrict__ A, const float* __restrict__ Wt,
    const float* __restrict__ bias, float* __restrict__ C)
{
    extern __shared__ __align__(16) char smem[];
    float (*As)[LDA] = (float(*)[LDA])smem;
    float (*Bs)[LDA] = (float(*)[LDA])(smem + 128 * LDA * 4);

    const int tid = threadIdx.x;
    const int wid = tid >> 5;
    const int lane = tid & 31;
    const int wm = wid & 1;
    const int wn = wid >> 1;
    const int g = lane >> 2;
    const int tig = lane & 3;

    const size_t m0 = (size_t)blockIdx.y * 128;
    const int n0 = blockIdx.x * 128;

    float acc[4][4][4];
#pragma unroll
    for (int mt = 0; mt < 4; mt++)
#pragma unroll
        for (int nt = 0; nt < 4; nt++)
#pragma unroll
            for (int q = 0; q < 4; q++) acc[mt][nt][q] = 0.f;

#pragma unroll
    for (int kt = 0; kt < 2; kt++) {
#pragma unroll
        for (int i = 0; i < 8; i++) {
            int idx = tid + i * 256;
            int row = idx >> 4;
            int c4  = idx & 15;
            float4 va = *(const float4*)&A[(m0 + row) * EMB + kt * KC + c4 * 4];
            va.x = to_tf32(va.x); va.y = to_tf32(va.y);
            va.z = to_tf32(va.z); va.w = to_tf32(va.w);
            *(float4*)&As[row][c4 * 4] = va;
            float4 vb = *(const float4*)&Wt[(size_t)(n0 + row) * EMB + kt * KC + c4 * 4];
            *(float4*)&Bs[row][c4 * 4] = vb;
        }
        __syncthreads();

#pragma unroll
        for (int k8 = 0; k8 < 8; k8++) {
            const int kb = k8 * 8;
            uint32_t af[4][4];
#pragma unroll
            for (int mt = 0; mt < 4; mt++) {
                int r = wm * 64 + mt * 16 + g;
                af[mt][0] = __float_as_uint(As[r][kb + tig]);
                af[mt][1] = __float_as_uint(As[r + 8][kb + tig]);
                af[mt][2] = __float_as_uint(As[r][kb + tig + 4]);
                af[mt][3] = __float_as_uint(As[r + 8][kb + tig + 4]);
            }
#pragma unroll
            for (int nt = 0; nt < 4; nt++) {
                int n = wn * 32 + nt * 8 + g;
                uint32_t b0 = __float_as_uint(Bs[n][kb + tig]);
                uint32_t b1 = __float_as_uint(Bs[n][kb + tig + 4]);
#pragma unroll
                for (int mt = 0; mt < 4; mt++)
                    mma_tf32(acc[mt][nt], af[mt], b0, b1);
            }
        }
        __syncthreads();
    }

#pragma unroll
    for (int nt = 0; nt < 4; nt++) {
        int col = n0 + wn * 32 + nt * 8 + 2 * tig;
        float b0 = bias[col], b1 = bias[col + 1];
#pragma unroll
        for (int mt = 0; mt < 4; mt++) {
            size_t row = m0 + wm * 64 + mt * 16 + g;
            float2 o0 = { acc[mt][nt][0] + b0, acc[mt][nt][1] + b1 };
            float2 o1 = { acc[mt][nt][2] + b0, acc[mt][nt][3] + b1 };
            *(float2*)&C[row * GATES + col] = o0;
            *(float2*)&C[(row + 8) * GATES + col] = o1;
        }
    }
}

// ---------------- W transpose + tf32 rounding ----------------
__global__ void transpose_w(const float* __restrict__ W, float* __restrict__ Wt)
{
    int idx = blockIdx.x * blockDim.x + threadIdx.x;
    if (idx < 4 * EMB * GATES) {
        int gsel = idx >> 16;
        int r = (idx >> 9) & 127;
        int c = idx & 511;
        Wt[(size_t)gsel * GATES * EMB + (size_t)c * EMB + r] = to_tf32(W[idx]);
    }
}

// ---------------- U fragment pre-swizzle (kt-pair interleaved for LDG.128) ----------------
__global__ void build_ufrag(const float* __restrict__ U, float* __restrict__ UF)
{
    int idx = blockIdx.x * blockDim.x + threadIdx.x;
    if (idx < 4 * 64 * 8 * 32 * 4) {
        int q    = idx & 3;
        int lane = (idx >> 2) & 31;
        int kt2  = (idx >> 7) & 7;
        int ntg  = (idx >> 10) & 63;
        int u    = idx >> 16;
        int tig = lane & 3, gg = lane >> 2;
        int kt = kt2 * 2 + (q >> 1);
        int p  = q & 1;
        int k = kt * 8 + tig + 4 * p;
        int n = ntg * 8 + gg;
        UF[idx] = to_tf32(U[(size_t)u * (EMB * GATES) + (size_t)k * GATES + n]);
    }
}

// ---------------- fused tensor-core LSTM recurrence ----------------
// grid (64, 2), block 512 (16 warps), 8 batch rows/block (m16 tile half-filled;
// rows 8-15 of h_s stay zero). Warp w owns gate quadruple cols {8w..8w+8}.
// UF loads software-pipelined one kt2 ahead to hide L2 latency.
__global__ __launch_bounds__(512) void lstm_tc(
    const float* __restrict__ zx_fw, const float* __restrict__ zx_bw,
    const float* __restrict__ uf_fw, const float* __restrict__ uf_bw,
    float* __restrict__ out_fw, float* __restrict__ out_bw)
{
    const int dir = blockIdx.y;
    const float* __restrict__ zx = dir ? zx_bw : zx_fw;
    const float* __restrict__ uf = dir ? uf_bw : uf_fw;
    float* __restrict__ out = dir ? out_bw : out_fw;

    const int b0  = blockIdx.x * 8;
    const int tid = threadIdx.x;
    const int w   = tid >> 5;
    const int lane = tid & 31;
    const int g = lane >> 2;
    const int tig = lane & 3;
    const int col0 = 8 * w + 2 * tig;

    __shared__ __align__(16) float h_s[2][16][132];   // ping-pong tf32 h; rows 8-15 zero

    for (int q2 = tid; q2 < 2 * 16 * 132; q2 += 512) ((float*)h_s)[q2] = 0.f;
    float c0 = 0.f, c1 = 0.f;

    const float4* ufp[4];
#pragma unroll
    for (int nt = 0; nt < 4; nt++)
        ufp[nt] = (const float4*)uf + (size_t)(w + 16 * nt) * 8 * 32 + lane;

    const float* zr0 = zx + ((size_t)(b0 + g) * SEQT) * GATES + col0;
    float* or0 = out + ((size_t)(b0 + g) * SEQT) * HID + col0;

    __syncthreads();

    for (int s = 0; s < SEQT; s++) {
        const int t = dir ? (SEQT - 1 - s) : s;
        const int rb = s & 1;
        const int wb = rb ^ 1;

        // prefetch zx (consumed after mma phase)
        float2 zv0[4];
#pragma unroll
        for (int nt = 0; nt < 4; nt++)
            zv0[nt] = *(const float2*)&zr0[(size_t)t * GATES + 128 * nt];

        // ---- mma phase: z = h @ U, UF pipelined one kt2 ahead ----
        float acc[4][4];
#pragma unroll
        for (int nt = 0; nt < 4; nt++)
#pragma unroll
            for (int q = 0; q < 4; q++) acc[nt][q] = 0.f;

        float4 bv[4];
#pragma unroll
        for (int nt = 0; nt < 4; nt++) bv[nt] = ufp[nt][0];

#pragma unroll
        for (int kt2 = 0; kt2 < 8; kt2++) {
            float4 nb[4];
            if (kt2 < 7) {
#pragma unroll
                for (int nt = 0; nt < 4; nt++) nb[nt] = ufp[nt][(kt2 + 1) * 32];
            }
            const int kbe = kt2 * 16;
            uint32_t ae[4], ao[4];
            ae[0] = __float_as_uint(h_s[rb][g][kbe + tig]);
            ae[1] = __float_as_uint(h_s[rb][g + 8][kbe + tig]);
            ae[2] = __float_as_uint(h_s[rb][g][kbe + tig + 4]);
            ae[3] = __float_as_uint(h_s[rb][g + 8][kbe + tig + 4]);
            ao[0] = __float_as_uint(h_s[rb][g][kbe + 8 + tig]);
            ao[1] = __float_as_uint(h_s[rb][g + 8][kbe + 8 + tig]);
            ao[2] = __float_as_uint(h_s[rb][g][kbe + 8 + tig + 4]);
            ao[3] = __float_as_uint(h_s[rb][g + 8][kbe + 8 + tig + 4]);
#pragma unroll
            for (int nt = 0; nt < 4; nt++) {
                mma_tf32(acc[nt], ae, __float_as_uint(bv[nt].x), __float_as_uint(bv[nt].y));
                mma_tf32(acc[nt], ao, __float_as_uint(bv[nt].z), __float_as_uint(bv[nt].w));
            }
#pragma unroll
            for (int nt = 0; nt < 4; nt++) bv[nt] = nb[nt];
        }

        // ---- gate phase: 2 cells (row g, cols col0, col0+1) ----
        float h00, h01;
        {
            float ig = sigm(acc[0][0] + zv0[0].x), fg = sigm(acc[1][0] + zv0[1].x);
            float gg = tanh_(acc[2][0] + zv0[2].x), og = sigm(acc[3][0] + zv0[3].x);
            c0 = fg * c0 + ig * gg;  h00 = og * tanh_(c0);
        }
        {
            float ig = sigm(acc[0][1] + zv0[0].y), fg = sigm(acc[1][1] + zv0[1].y);
            float gg = tanh_(acc[2][1] + zv0[2].y), og = sigm(acc[3][1] + zv0[3].y);
            c1 = fg * c1 + ig * gg;  h01 = og * tanh_(c1);
        }

        *(float2*)&h_s[wb][g][col0] = make_float2(to_tf32(h00), to_tf32(h01));
        *(float2*)&or0[(size_t)t * HID] = make_float2(h00, h01);

        __syncthreads();
    }
}

// ---------------- final combine ----------------
__global__ void combine(const float* __restrict__ a, const float* __restrict__ b,
                        const float* __restrict__ c, const float* __restrict__ d,
                        float* __restrict__ out, int n4)
{
    int i = blockIdx.x * blockDim.x + threadIdx.x;
    if (i < n4) {
        float4 va = ((const float4*)a)[i];
        float4 vb = ((const float4*)b)[i];
        float4 vc = ((const float4*)c)[i];
        float4 vd = ((const float4*)d)[i];
        float4 o;
        o.x = 0.5f * (va.x + vb.x + vc.x + vd.x);
        o.y = 0.5f * (va.y + vb.y + vc.y + vd.y);
        o.z = 0.5f * (va.z + vb.z + vc.z + vd.z);
        o.w = 0.5f * (va.w + vb.w + vc.w + vd.w);
        ((float4*)out)[i] = o;
    }
}

// ---------------- launch ----------------
extern "C" void kernel_launch(void* const* d_in, const int* in_sizes, int n_in,
                              void* d_out, int out_size)
{
    const float* x = (const float*)d_in[0];
    const float* W = (const float*)d_in[1];
    const float* U = (const float*)d_in[2];
    const float* b = (const float*)d_in[3];

    float *zxf, *zxb, *s0f, *s0b, *s1f, *s1b, *Wt, *UF;
    cudaGetSymbolAddress((void**)&zxf, g_zx_fw);
    cudaGetSymbolAddress((void**)&zxb, g_zx_bw);
    cudaGetSymbolAddress((void**)&s0f, g_s0f);
    cudaGetSymbolAddress((void**)&s0b, g_s0b);
    cudaGetSymbolAddress((void**)&s1f, g_s1f);
    cudaGetSymbolAddress((void**)&s1b, g_s1b);
    cudaGetSymbolAddress((void**)&Wt, g_Wt);
    cudaGetSymbolAddress((void**)&UF, g_Ufrag);

    cudaFuncSetAttribute(gemm_tc, cudaFuncAttributeMaxDynamicSharedMemorySize, GSMEM);

    const size_t WSZ = (size_t)EMB * GATES;   // 65536
    const float* b00 = b;           const float* b01 = b + GATES;
    const float* b10 = b + 2*GATES; const float* b11 = b + 3*GATES;
    float* Wt00 = Wt;           float* Wt01 = Wt + WSZ;
    float* Wt10 = Wt + 2*WSZ;   float* Wt11 = Wt + 3*WSZ;
    float* UF00 = UF;           float* UF01 = UF + WSZ;
    float* UF10 = UF + 2*WSZ;   float* UF11 = UF + 3*WSZ;

    transpose_w<<<(4 * EMB * GATES + 255) / 256, 256>>>(W, Wt);
    build_ufrag<<<(4 * EMB * GATES + 255) / 256, 256>>>(U, UF);

    dim3 gg(GATES / 128, MTOT / 128);   // (4, 800)
    dim3 lg(BATCH / 8, 2);              // (64, 2) -> 128 blocks

    gemm_tc<<<gg, 256, GSMEM>>>(x, Wt00, b00, zxf);
    gemm_tc<<<gg, 256, GSMEM>>>(x, Wt01, b01, zxb);
    lstm_tc<<<lg, 512>>>(zxf, zxb, UF00, UF01, s0f, s0b);

    gemm_tc<<<gg, 256, GSMEM>>>(s0f, Wt10, b10, zxf);
    gemm_tc<<<gg, 256, GSMEM>>>(s0b, Wt11, b11, zxb);
    lstm_tc<<<lg, 512>>>(zxf, zxb, UF10, UF11, s1f, s1b);

    int n4 = MTOT * HID / 4;
    combine<<<(n4 + 255) / 256, 256>>>(s1f, s0f, s1b, s0b, (float*)d_out, n4);
}

// round 9
// speedup vs baseline: 4.0706x; 1.7626x over previous
#include <cuda_runtime.h>
#include <cuda_bf16.h>
#include <math.h>
#include <stdint.h>

#define BATCH 512
#define SEQT  200
#define HID   128
#define GATES 512   // 4H
#define EMB   128
#define MTOT  (BATCH*SEQT)   // 102400

// ---------------- static scratch ----------------
__device__ float g_zx_fw[(size_t)MTOT * GATES];
__device__ float g_zx_bw[(size_t)MTOT * GATES];
__device__ float g_s0f[(size_t)MTOT * HID];
__device__ float g_s0b[(size_t)MTOT * HID];
__device__ float g_s1f[(size_t)MTOT * HID];
__device__ float g_s1b[(size_t)MTOT * HID];
__device__ float g_Wt[4 * GATES * EMB];              // transposed + tf32-rounded W
__device__ uint32_t g_UfragB[4 * 64 * 4 * 32 * 4];   // bf16 U fragments (m16n8k16), kt-pair packed

// ---------------- helpers ----------------
__device__ __forceinline__ float to_tf32(float x) {
    uint32_t y;
    asm("cvt.rna.tf32.f32 %0, %1;" : "=r"(y) : "f"(x));
    return __uint_as_float(y);
}
__device__ __forceinline__ float rcp_(float x) {
    float y; asm("rcp.approx.f32 %0, %1;" : "=f"(y) : "f"(x)); return y;
}
__device__ __forceinline__ float ex2_(float x) {
    float y; asm("ex2.approx.f32 %0, %1;" : "=f"(y) : "f"(x)); return y;
}
__device__ __forceinline__ float sigm(float x) {
    return rcp_(1.f + ex2_(-1.4426950408889634f * x));
}
__device__ __forceinline__ float tanh_(float x) {
    return 1.f - 2.f * rcp_(1.f + ex2_(2.8853900817779268f * x));
}

__device__ __forceinline__ void mma_tf32(float* d, const uint32_t* a, uint32_t b0, uint32_t b1) {
    asm volatile(
        "mma.sync.aligned.m16n8k8.row.col.f32.tf32.tf32.f32 "
        "{%0,%1,%2,%3}, {%4,%5,%6,%7}, {%8,%9}, {%0,%1,%2,%3};"
        : "+f"(d[0]), "+f"(d[1]), "+f"(d[2]), "+f"(d[3])
        : "r"(a[0]), "r"(a[1]), "r"(a[2]), "r"(a[3]), "r"(b0), "r"(b1));
}
__device__ __forceinline__ void mma_bf16(float* d, const uint32_t* a, uint32_t b0, uint32_t b1) {
    asm volatile(
        "mma.sync.aligned.m16n8k16.row.col.f32.bf16.bf16.f32 "
        "{%0,%1,%2,%3}, {%4,%5,%6,%7}, {%8,%9}, {%0,%1,%2,%3};"
        : "+f"(d[0]), "+f"(d[1]), "+f"(d[2]), "+f"(d[3])
        : "r"(a[0]), "r"(a[1]), "r"(a[2]), "r"(a[3]), "r"(b0), "r"(b1));
}

// ---------------- tensor-core GEMM (unchanged) ----------------
#define KC 64
#define LDA 68
#define GSMEM (2 * 128 * LDA * 4)

__global__ __launch_bounds__(256) void gemm_tc(
    const float* __restrict__ A, const float* __restrict__ Wt,
    const float* __restrict__ bias, float* __restrict__ C)
{
    extern __shared__ __align__(16) char smem[];
    float (*As)[LDA] = (float(*)[LDA])smem;
    float (*Bs)[LDA] = (float(*)[LDA])(smem + 128 * LDA * 4);

    const int tid = threadIdx.x;
    const int wid = tid >> 5;
    const int lane = tid & 31;
    const int wm = wid & 1;
    const int wn = wid >> 1;
    const int g = lane >> 2;
    const int tig = lane & 3;

    const size_t m0 = (size_t)blockIdx.y * 128;
    const int n0 = blockIdx.x * 128;

    float acc[4][4][4];
#pragma unroll
    for (int mt = 0; mt < 4; mt++)
#pragma unroll
        for (int nt = 0; nt < 4; nt++)
#pragma unroll
            for (int q = 0; q < 4; q++) acc[mt][nt][q] = 0.f;

#pragma unroll
    for (int kt = 0; kt < 2; kt++) {
#pragma unroll
        for (int i = 0; i < 8; i++) {
            int idx = tid + i * 256;
            int row = idx >> 4;
            int c4  = idx & 15;
            float4 va = *(const float4*)&A[(m0 + row) * EMB + kt * KC + c4 * 4];
            va.x = to_tf32(va.x); va.y = to_tf32(va.y);
            va.z = to_tf32(va.z); va.w = to_tf32(va.w);
            *(float4*)&As[row][c4 * 4] = va;
            float4 vb = *(const float4*)&Wt[(size_t)(n0 + row) * EMB + kt * KC + c4 * 4];
            *(float4*)&Bs[row][c4 * 4] = vb;
        }
        __syncthreads();

#pragma unroll
        for (int k8 = 0; k8 < 8; k8++) {
            const int kb = k8 * 8;
            uint32_t af[4][4];
#pragma unroll
            for (int mt = 0; mt < 4; mt++) {
                int r = wm * 64 + mt * 16 + g;
                af[mt][0] = __float_as_uint(As[r][kb + tig]);
                af[mt][1] = __float_as_uint(As[r + 8][kb + tig]);
                af[mt][2] = __float_as_uint(As[r][kb + tig + 4]);
                af[mt][3] = __float_as_uint(As[r + 8][kb + tig + 4]);
            }
#pragma unroll
            for (int nt = 0; nt < 4; nt++) {
                int n = wn * 32 + nt * 8 + g;
                uint32_t b0 = __float_as_uint(Bs[n][kb + tig]);
                uint32_t b1 = __float_as_uint(Bs[n][kb + tig + 4]);
#pragma unroll
                for (int mt = 0; mt < 4; mt++)
                    mma_tf32(acc[mt][nt], af[mt], b0, b1);
            }
        }
        __syncthreads();
    }

#pragma unroll
    for (int nt = 0; nt < 4; nt++) {
        int col = n0 + wn * 32 + nt * 8 + 2 * tig;
        float b0 = bias[col], b1 = bias[col + 1];
#pragma unroll
        for (int mt = 0; mt < 4; mt++) {
            size_t row = m0 + wm * 64 + mt * 16 + g;
            float2 o0 = { acc[mt][nt][0] + b0, acc[mt][nt][1] + b1 };
            float2 o1 = { acc[mt][nt][2] + b0, acc[mt][nt][3] + b1 };
            *(float2*)&C[row * GATES + col] = o0;
            *(float2*)&C[(row + 8) * GATES + col] = o1;
        }
    }
}

// ---------------- W transpose + tf32 rounding ----------------
__global__ void transpose_w(const float* __restrict__ W, float* __restrict__ Wt)
{
    int idx = blockIdx.x * blockDim.x + threadIdx.x;
    if (idx < 4 * EMB * GATES) {
        int gsel = idx >> 16;
        int r = (idx >> 9) & 127;
        int c = idx & 511;
        Wt[(size_t)gsel * GATES * EMB + (size_t)c * EMB + r] = to_tf32(W[idx]);
    }
}

// ---------------- bf16 U fragment pre-swizzle (m16n8k16, kt-pair packed) ----------------
// UFB[u][ntg 64][kt2 4][lane 32][q 4] (uint32 = bf16x2):
//   kt = 2*kt2 + (q>>1); reg = q&1; tig=lane&3; g=lane>>2; n = ntg*8+g;
//   k_lo = kt*16 + reg*8 + 2*tig; value = {bf16(U[k_lo][n]) lo, bf16(U[k_lo+1][n]) hi}
__global__ void build_ufragb(const float* __restrict__ U, uint32_t* __restrict__ UFB)
{
    int idx = blockIdx.x * blockDim.x + threadIdx.x;
    if (idx < 4 * 64 * 4 * 32 * 4) {
        int q    = idx & 3;
        int lane = (idx >> 2) & 31;
        int kt2  = (idx >> 7) & 3;
        int ntg  = (idx >> 9) & 63;
        int u    = idx >> 15;
        int tig = lane & 3, gg = lane >> 2;
        int kt  = kt2 * 2 + (q >> 1);
        int reg = q & 1;
        int k_lo = kt * 16 + reg * 8 + 2 * tig;
        int n = ntg * 8 + gg;
        const float* Ub = U + (size_t)u * (EMB * GATES);
        __nv_bfloat162 v = __floats2bfloat162_rn(Ub[(size_t)k_lo * GATES + n],
                                                 Ub[(size_t)(k_lo + 1) * GATES + n]);
        UFB[idx] = *(uint32_t*)&v;
    }
}

// ---------------- fused bf16 tensor-core LSTM recurrence ----------------
// grid (64, 2), block 512 (16 warps), 8 batch rows/block (m16 half-filled).
// Warp w owns gate quadruple cols {8w..8w+8}. m16n8k16 bf16: 32 mma/warp/step.
// h kept as bf16x2 in ping-pong smem; UF loads pipelined one kt2 ahead.
__global__ __launch_bounds__(512) void lstm_tc(
    const float* __restrict__ zx_fw, const float* __restrict__ zx_bw,
    const uint32_t* __restrict__ uf_fw, const uint32_t* __restrict__ uf_bw,
    float* __restrict__ out_fw, float* __restrict__ out_bw)
{
    const int dir = blockIdx.y;
    const float* __restrict__ zx = dir ? zx_bw : zx_fw;
    const uint32_t* __restrict__ uf = dir ? uf_bw : uf_fw;
    float* __restrict__ out = dir ? out_bw : out_fw;

    const int b0  = blockIdx.x * 8;
    const int tid = threadIdx.x;
    const int w   = tid >> 5;
    const int lane = tid & 31;
    const int g = lane >> 2;
    const int tig = lane & 3;
    const int col0 = 8 * w + 2 * tig;

    // h as bf16x2: h2[buf][row 16][half2 col 64 + 4 pad]; rows 8-15 stay zero
    __shared__ __align__(16) uint32_t h2[2][16][68];

    for (int q2 = tid; q2 < 2 * 16 * 68; q2 += 512) ((uint32_t*)h2)[q2] = 0u;
    float c0 = 0.f, c1 = 0.f;

    const uint4* ufp[4];
#pragma unroll
    for (int nt = 0; nt < 4; nt++)
        ufp[nt] = (const uint4*)uf + (size_t)(w + 16 * nt) * 4 * 32 + lane;

    const float* zr0 = zx + ((size_t)(b0 + g) * SEQT) * GATES + col0;
    float* or0 = out + ((size_t)(b0 + g) * SEQT) * HID + col0;

    __syncthreads();

    for (int s = 0; s < SEQT; s++) {
        const int t = dir ? (SEQT - 1 - s) : s;
        const int rb = s & 1;
        const int wb = rb ^ 1;

        // prefetch zx (consumed after mma phase)
        float2 zv0[4];
#pragma unroll
        for (int nt = 0; nt < 4; nt++)
            zv0[nt] = *(const float2*)&zr0[(size_t)t * GATES + 128 * nt];

        // ---- mma phase: z = h @ U (bf16 m16n8k16), UF pipelined one kt2 ahead ----
        float acc[4][4];
#pragma unroll
        for (int nt = 0; nt < 4; nt++)
#pragma unroll
            for (int q = 0; q < 4; q++) acc[nt][q] = 0.f;

        uint4 bv[4];
#pragma unroll
        for (int nt = 0; nt < 4; nt++) bv[nt] = ufp[nt][0];

#pragma unroll
        for (int kt2 = 0; kt2 < 4; kt2++) {
            uint4 nb[4];
            if (kt2 < 3) {
#pragma unroll
                for (int nt = 0; nt < 4; nt++) nb[nt] = ufp[nt][(kt2 + 1) * 32];
            }
            // A fragments for kt = 2*kt2 (even) and 2*kt2+1 (odd); h2 row = 8 half2/kt
            const int kbe = kt2 * 16;       // half2 base for even kt
            uint32_t ae[4], ao[4];
            ae[0] = h2[rb][g][kbe + tig];
            ae[1] = h2[rb][g + 8][kbe + tig];
            ae[2] = h2[rb][g][kbe + tig + 4];
            ae[3] = h2[rb][g + 8][kbe + tig + 4];
            ao[0] = h2[rb][g][kbe + 8 + tig];
            ao[1] = h2[rb][g + 8][kbe + 8 + tig];
            ao[2] = h2[rb][g][kbe + 8 + tig + 4];
            ao[3] = h2[rb][g + 8][kbe + 8 + tig + 4];
#pragma unroll
            for (int nt = 0; nt < 4; nt++) {
                mma_bf16(acc[nt], ae, bv[nt].x, bv[nt].y);
                mma_bf16(acc[nt], ao, bv[nt].z, bv[nt].w);
            }
#pragma unroll
            for (int nt = 0; nt < 4; nt++) bv[nt] = nb[nt];
        }

        // ---- gate phase: 2 cells (row g, cols col0, col0+1) ----
        float h00, h01;
        {
            float ig = sigm(acc[0][0] + zv0[0].x), fg = sigm(acc[1][0] + zv0[1].x);
            float gg = tanh_(acc[2][0] + zv0[2].x), og = sigm(acc[3][0] + zv0[3].x);
            c0 = fg * c0 + ig * gg;  h00 = og * tanh_(c0);
        }
        {
            float ig = sigm(acc[0][1] + zv0[0].y), fg = sigm(acc[1][1] + zv0[1].y);
            float gg = tanh_(acc[2][1] + zv0[2].y), og = sigm(acc[3][1] + zv0[3].y);
            c1 = fg * c1 + ig * gg;  h01 = og * tanh_(c1);
        }

        // bf16x2 h to next-step buffer (low = col0, high = col0+1); fp32 h to gmem
        {
            __nv_bfloat162 hp = __floats2bfloat162_rn(h00, h01);
            h2[wb][g][col0 >> 1] = *(uint32_t*)&hp;
        }
        *(float2*)&or0[(size_t)t * HID] = make_float2(h00, h01);

        __syncthreads();
    }
}

// ---------------- final combine ----------------
__global__ void combine(const float* __restrict__ a, const float* __restrict__ b,
                        const float* __restrict__ c, const float* __restrict__ d,
                        float* __restrict__ out, int n4)
{
    int i = blockIdx.x * blockDim.x + threadIdx.x;
    if (i < n4) {
        float4 va = ((const float4*)a)[i];
        float4 vb = ((const float4*)b)[i];
        float4 vc = ((const float4*)c)[i];
        float4 vd = ((const float4*)d)[i];
        float4 o;
        o.x = 0.5f * (va.x + vb.x + vc.x + vd.x);
        o.y = 0.5f * (va.y + vb.y + vc.y + vd.y);
        o.z = 0.5f * (va.z + vb.z + vc.z + vd.z);
        o.w = 0.5f * (va.w + vb.w + vc.w + vd.w);
        ((float4*)out)[i] = o;
    }
}

// ---------------- launch ----------------
extern "C" void kernel_launch(void* const* d_in, const int* in_sizes, int n_in,
                              void* d_out, int out_size)
{
    const float* x = (const float*)d_in[0];
    const float* W = (const float*)d_in[1];
    const float* U = (const float*)d_in[2];
    const float* b = (const float*)d_in[3];

    float *zxf, *zxb, *s0f, *s0b, *s1f, *s1b, *Wt;
    uint32_t *UFB;
    cudaGetSymbolAddress((void**)&zxf, g_zx_fw);
    cudaGetSymbolAddress((void**)&zxb, g_zx_bw);
    cudaGetSymbolAddress((void**)&s0f, g_s0f);
    cudaGetSymbolAddress((void**)&s0b, g_s0b);
    cudaGetSymbolAddress((void**)&s1f, g_s1f);
    cudaGetSymbolAddress((void**)&s1b, g_s1b);
    cudaGetSymbolAddress((void**)&Wt, g_Wt);
    cudaGetSymbolAddress((void**)&UFB, g_UfragB);

    cudaFuncSetAttribute(gemm_tc, cudaFuncAttributeMaxDynamicSharedMemorySize, GSMEM);

    const size_t WSZ = (size_t)EMB * GATES;   // 65536
    const size_t UFSZ = 64 * 4 * 32 * 4;      // 32768 uint32 per (layer,dir)
    const float* b00 = b;           const float* b01 = b + GATES;
    const float* b10 = b + 2*GATES; const float* b11 = b + 3*GATES;
    float* Wt00 = Wt;           float* Wt01 = Wt + WSZ;
    float* Wt10 = Wt + 2*WSZ;   float* Wt11 = Wt + 3*WSZ;
    uint32_t* UF00 = UFB;            uint32_t* UF01 = UFB + UFSZ;
    uint32_t* UF10 = UFB + 2*UFSZ;   uint32_t* UF11 = UFB + 3*UFSZ;

    transpose_w<<<(4 * EMB * GATES + 255) / 256, 256>>>(W, Wt);
    build_ufragb<<<(4 * 64 * 4 * 32 * 4 + 255) / 256, 256>>>(U, UFB);

    dim3 gg(GATES / 128, MTOT / 128);   // (4, 800)
    dim3 lg(BATCH / 8, 2);              // (64, 2) -> 128 blocks

    gemm_tc<<<gg, 256, GSMEM>>>(x, Wt00, b00, zxf);
    gemm_tc<<<gg, 256, GSMEM>>>(x, Wt01, b01, zxb);
    lstm_tc<<<lg, 512>>>(zxf, zxb, UF00, UF01, s0f, s0b);

    gemm_tc<<<gg, 256, GSMEM>>>(s0f, Wt10, b10, zxf);
    gemm_tc<<<gg, 256, GSMEM>>>(s0b, Wt11, b11, zxb);
    lstm_tc<<<lg, 512>>>(zxf, zxb, UF10, UF11, s1f, s1b);

    int n4 = MTOT * HID / 4;
    combine<<<(n4 + 255) / 256, 256>>>(s1f, s0f, s1b, s0b, (float*)d_out, n4);
}

// round 10
// speedup vs baseline: 4.8126x; 1.1823x over previous
#include <cuda_runtime.h>
#include <cuda_bf16.h>
#include <math.h>
#include <stdint.h>

#define BATCH 512
#define SEQT  200
#define HID   128
#define GATES 512   // 4H
#define EMB   128
#define MTOT  (BATCH*SEQT)   // 102400

// ---------------- static scratch ----------------
__device__ float g_zx_fw[(size_t)MTOT * GATES];
__device__ float g_zx_bw[(size_t)MTOT * GATES];
__device__ float g_s0f[(size_t)MTOT * HID];
__device__ float g_s0b[(size_t)MTOT * HID];
__device__ float g_s1f[(size_t)MTOT * HID];
__device__ float g_s1b[(size_t)MTOT * HID];
__device__ uint32_t g_Wtb[4 * GATES * (EMB/2)];      // bf16x2 W^T: [4][n=512][k2=64]
__device__ uint32_t g_UfragB[4 * 64 * 4 * 32 * 4];   // bf16 U fragments (m16n8k16)

// ---------------- helpers ----------------
__device__ __forceinline__ float rcp_(float x) {
    float y; asm("rcp.approx.f32 %0, %1;" : "=f"(y) : "f"(x)); return y;
}
__device__ __forceinline__ float ex2_(float x) {
    float y; asm("ex2.approx.f32 %0, %1;" : "=f"(y) : "f"(x)); return y;
}
__device__ __forceinline__ float sigm(float x) {
    return rcp_(1.f + ex2_(-1.4426950408889634f * x));
}
__device__ __forceinline__ float tanh_(float x) {
    return 1.f - 2.f * rcp_(1.f + ex2_(2.8853900817779268f * x));
}
__device__ __forceinline__ uint32_t bf2(float lo, float hi) {
    __nv_bfloat162 v = __floats2bfloat162_rn(lo, hi);
    return *(uint32_t*)&v;
}

__device__ __forceinline__ void mma_bf16(float* d, const uint32_t* a, uint32_t b0, uint32_t b1) {
    asm volatile(
        "mma.sync.aligned.m16n8k16.row.col.f32.bf16.bf16.f32 "
        "{%0,%1,%2,%3}, {%4,%5,%6,%7}, {%8,%9}, {%0,%1,%2,%3};"
        : "+f"(d[0]), "+f"(d[1]), "+f"(d[2]), "+f"(d[3])
        : "r"(a[0]), "r"(a[1]), "r"(a[2]), "r"(a[3]), "r"(b0), "r"(b1));
}

// ---------------- bf16 tensor-core GEMM: C[m,n] = A[m,k] @ Wt[n,k]^T + bias[n] ----------------
// A fp32 [MTOT,128] -> bf16 staged; Wtb bf16x2 [512][64]. Tile M=128,N=128,K=128 single pass.
// 256 thr = 8 warps (2m x 4n); warp tile 64x32; m16n8k16.
#define LDB2 68   // uint32 stride; 68%32==4 -> conflict-free fragment loads
#define GSMEM (2 * 128 * LDB2 * 4)   // ~68KB

__global__ __launch_bounds__(256) void gemm_bf(
    const float* __restrict__ A, const uint32_t* __restrict__ Wtb,
    const float* __restrict__ bias, float* __restrict__ C)
{
    extern __shared__ __align__(16) char smem[];
    uint32_t (*As2)[LDB2] = (uint32_t(*)[LDB2])smem;                         // [128][68] bf16x2 along k
    uint32_t (*Bs2)[LDB2] = (uint32_t(*)[LDB2])(smem + 128 * LDB2 * 4);      // [128][68]

    const int tid = threadIdx.x;
    const int wid = tid >> 5;
    const int lane = tid & 31;
    const int wm = wid & 1;
    const int wn = wid >> 1;
    const int g = lane >> 2;
    const int tig = lane & 3;

    const size_t m0 = (size_t)blockIdx.y * 128;
    const int n0 = blockIdx.x * 128;

    // stage A: 128 rows x 32 float4 -> bf16x2 pairs
#pragma unroll
    for (int i = 0; i < 16; i++) {
        int idx = tid + i * 256;       // 0..4095
        int row = idx >> 5;
        int c4  = idx & 31;
        float4 va = *(const float4*)&A[(m0 + row) * EMB + c4 * 4];
        uint2 u = { bf2(va.x, va.y), bf2(va.z, va.w) };
        *(uint2*)&As2[row][c4 * 2] = u;
    }
    // stage B: 128 rows x 16 uint4
#pragma unroll
    for (int i = 0; i < 8; i++) {
        int idx = tid + i * 256;       // 0..2047
        int row = idx >> 4;
        int c4  = idx & 15;
        uint4 v = *(const uint4*)&Wtb[(size_t)(n0 + row) * (EMB/2) + c4 * 4];
        *(uint4*)&Bs2[row][c4 * 4] = v;
    }
    __syncthreads();

    float acc[4][4][4];
#pragma unroll
    for (int mt = 0; mt < 4; mt++)
#pragma unroll
        for (int nt = 0; nt < 4; nt++)
#pragma unroll
            for (int q = 0; q < 4; q++) acc[mt][nt][q] = 0.f;

#pragma unroll
    for (int k8 = 0; k8 < 8; k8++) {
        const int kh = k8 * 8;
        uint32_t af[4][4];
#pragma unroll
        for (int mt = 0; mt < 4; mt++) {
            int r = wm * 64 + mt * 16 + g;
            af[mt][0] = As2[r][kh + tig];
            af[mt][1] = As2[r + 8][kh + tig];
            af[mt][2] = As2[r][kh + 4 + tig];
            af[mt][3] = As2[r + 8][kh + 4 + tig];
        }
#pragma unroll
        for (int nt = 0; nt < 4; nt++) {
            int n = wn * 32 + nt * 8 + g;
            uint32_t b0 = Bs2[n][kh + tig];
            uint32_t b1 = Bs2[n][kh + 4 + tig];
#pragma unroll
            for (int mt = 0; mt < 4; mt++)
                mma_bf16(acc[mt][nt], af[mt], b0, b1);
        }
    }

#pragma unroll
    for (int nt = 0; nt < 4; nt++) {
        int col = n0 + wn * 32 + nt * 8 + 2 * tig;
        float b0 = bias[col], b1 = bias[col + 1];
#pragma unroll
        for (int mt = 0; mt < 4; mt++) {
            size_t row = m0 + wm * 64 + mt * 16 + g;
            float2 o0 = { acc[mt][nt][0] + b0, acc[mt][nt][1] + b1 };
            float2 o1 = { acc[mt][nt][2] + b0, acc[mt][nt][3] + b1 };
            *(float2*)&C[row * GATES + col] = o0;
            *(float2*)&C[(row + 8) * GATES + col] = o1;
        }
    }
}

// ---------------- W -> bf16x2 transposed: Wtb[u][n][k2] ----------------
__global__ void build_wtb(const float* __restrict__ W, uint32_t* __restrict__ Wtb)
{
    int idx = blockIdx.x * blockDim.x + threadIdx.x;   // over 4*512*64
    if (idx < 4 * GATES * (EMB/2)) {
        int k2 = idx & 63;
        int n  = (idx >> 6) & 511;
        int u  = idx >> 15;
        const float* Wb = W + (size_t)u * (EMB * GATES);
        Wtb[idx] = bf2(Wb[(size_t)(2*k2) * GATES + n], Wb[(size_t)(2*k2+1) * GATES + n]);
    }
}

// ---------------- bf16 U fragment pre-swizzle (m16n8k16, kt-pair packed) ----------------
__global__ void build_ufragb(const float* __restrict__ U, uint32_t* __restrict__ UFB)
{
    int idx = blockIdx.x * blockDim.x + threadIdx.x;
    if (idx < 4 * 64 * 4 * 32 * 4) {
        int q    = idx & 3;
        int lane = (idx >> 2) & 31;
        int kt2  = (idx >> 7) & 3;
        int ntg  = (idx >> 9) & 63;
        int u    = idx >> 15;
        int tig = lane & 3, gg = lane >> 2;
        int kt  = kt2 * 2 + (q >> 1);
        int reg = q & 1;
        int k_lo = kt * 16 + reg * 8 + 2 * tig;
        int n = ntg * 8 + gg;
        const float* Ub = U + (size_t)u * (EMB * GATES);
        UFB[idx] = bf2(Ub[(size_t)k_lo * GATES + n], Ub[(size_t)(k_lo + 1) * GATES + n]);
    }
}

// ---------------- fused bf16 tensor-core LSTM recurrence (unchanged from round 9) ----------------
__global__ __launch_bounds__(512) void lstm_tc(
    const float* __restrict__ zx_fw, const float* __restrict__ zx_bw,
    const uint32_t* __restrict__ uf_fw, const uint32_t* __restrict__ uf_bw,
    float* __restrict__ out_fw, float* __restrict__ out_bw)
{
    const int dir = blockIdx.y;
    const float* __restrict__ zx = dir ? zx_bw : zx_fw;
    const uint32_t* __restrict__ uf = dir ? uf_bw : uf_fw;
    float* __restrict__ out = dir ? out_bw : out_fw;

    const int b0  = blockIdx.x * 8;
    const int tid = threadIdx.x;
    const int w   = tid >> 5;
    const int lane = tid & 31;
    const int g = lane >> 2;
    const int tig = lane & 3;
    const int col0 = 8 * w + 2 * tig;

    __shared__ __align__(16) uint32_t h2[2][16][68];

    for (int q2 = tid; q2 < 2 * 16 * 68; q2 += 512) ((uint32_t*)h2)[q2] = 0u;
    float c0 = 0.f, c1 = 0.f;

    const uint4* ufp[4];
#pragma unroll
    for (int nt = 0; nt < 4; nt++)
        ufp[nt] = (const uint4*)uf + (size_t)(w + 16 * nt) * 4 * 32 + lane;

    const float* zr0 = zx + ((size_t)(b0 + g) * SEQT) * GATES + col0;
    float* or0 = out + ((size_t)(b0 + g) * SEQT) * HID + col0;

    __syncthreads();

    for (int s = 0; s < SEQT; s++) {
        const int t = dir ? (SEQT - 1 - s) : s;
        const int rb = s & 1;
        const int wb = rb ^ 1;

        float2 zv0[4];
#pragma unroll
        for (int nt = 0; nt < 4; nt++)
            zv0[nt] = *(const float2*)&zr0[(size_t)t * GATES + 128 * nt];

        float acc[4][4];
#pragma unroll
        for (int nt = 0; nt < 4; nt++)
#pragma unroll
            for (int q = 0; q < 4; q++) acc[nt][q] = 0.f;

        uint4 bv[4];
#pragma unroll
        for (int nt = 0; nt < 4; nt++) bv[nt] = ufp[nt][0];

#pragma unroll
        for (int kt2 = 0; kt2 < 4; kt2++) {
            uint4 nb[4];
            if (kt2 < 3) {
#pragma unroll
                for (int nt = 0; nt < 4; nt++) nb[nt] = ufp[nt][(kt2 + 1) * 32];
            }
            const int kbe = kt2 * 16;
            uint32_t ae[4], ao[4];
            ae[0] = h2[rb][g][kbe + tig];
            ae[1] = h2[rb][g + 8][kbe + tig];
            ae[2] = h2[rb][g][kbe + tig + 4];
            ae[3] = h2[rb][g + 8][kbe + tig + 4];
            ao[0] = h2[rb][g][kbe + 8 + tig];
            ao[1] = h2[rb][g + 8][kbe + 8 + tig];
            ao[2] = h2[rb][g][kbe + 8 + tig + 4];
            ao[3] = h2[rb][g + 8][kbe + 8 + tig + 4];
#pragma unroll
            for (int nt = 0; nt < 4; nt++) {
                mma_bf16(acc[nt], ae, bv[nt].x, bv[nt].y);
                mma_bf16(acc[nt], ao, bv[nt].z, bv[nt].w);
            }
#pragma unroll
            for (int nt = 0; nt < 4; nt++) bv[nt] = nb[nt];
        }

        float h00, h01;
        {
            float ig = sigm(acc[0][0] + zv0[0].x), fg = sigm(acc[1][0] + zv0[1].x);
            float gg = tanh_(acc[2][0] + zv0[2].x), og = sigm(acc[3][0] + zv0[3].x);
            c0 = fg * c0 + ig * gg;  h00 = og * tanh_(c0);
        }
        {
            float ig = sigm(acc[0][1] + zv0[0].y), fg = sigm(acc[1][1] + zv0[1].y);
            float gg = tanh_(acc[2][1] + zv0[2].y), og = sigm(acc[3][1] + zv0[3].y);
            c1 = fg * c1 + ig * gg;  h01 = og * tanh_(c1);
        }

        h2[wb][g][col0 >> 1] = bf2(h00, h01);
        *(float2*)&or0[(size_t)t * HID] = make_float2(h00, h01);

        __syncthreads();
    }
}

// ---------------- final combine ----------------
__global__ void combine(const float* __restrict__ a, const float* __restrict__ b,
                        const float* __restrict__ c, const float* __restrict__ d,
                        float* __restrict__ out, int n4)
{
    int i = blockIdx.x * blockDim.x + threadIdx.x;
    if (i < n4) {
        float4 va = ((const float4*)a)[i];
        float4 vb = ((const float4*)b)[i];
        float4 vc = ((const float4*)c)[i];
        float4 vd = ((const float4*)d)[i];
        float4 o;
        o.x = 0.5f * (va.x + vb.x + vc.x + vd.x);
        o.y = 0.5f * (va.y + vb.y + vc.y + vd.y);
        o.z = 0.5f * (va.z + vb.z + vc.z + vd.z);
        o.w = 0.5f * (va.w + vb.w + vc.w + vd.w);
        ((float4*)out)[i] = o;
    }
}

// ---------------- launch ----------------
extern "C" void kernel_launch(void* const* d_in, const int* in_sizes, int n_in,
                              void* d_out, int out_size)
{
    const float* x = (const float*)d_in[0];
    const float* W = (const float*)d_in[1];
    const float* U = (const float*)d_in[2];
    const float* b = (const float*)d_in[3];

    float *zxf, *zxb, *s0f, *s0b, *s1f, *s1b;
    uint32_t *Wtb, *UFB;
    cudaGetSymbolAddress((void**)&zxf, g_zx_fw);
    cudaGetSymbolAddress((void**)&zxb, g_zx_bw);
    cudaGetSymbolAddress((void**)&s0f, g_s0f);
    cudaGetSymbolAddress((void**)&s0b, g_s0b);
    cudaGetSymbolAddress((void**)&s1f, g_s1f);
    cudaGetSymbolAddress((void**)&s1b, g_s1b);
    cudaGetSymbolAddress((void**)&Wtb, g_Wtb);
    cudaGetSymbolAddress((void**)&UFB, g_UfragB);

    cudaFuncSetAttribute(gemm_bf, cudaFuncAttributeMaxDynamicSharedMemorySize, GSMEM);

    const size_t WBSZ = (size_t)GATES * (EMB/2);   // 32768 uint32
    const size_t UFSZ = 64 * 4 * 32 * 4;           // 32768 uint32
    const float* b00 = b;           const float* b01 = b + GATES;
    const float* b10 = b + 2*GATES; const float* b11 = b + 3*GATES;
    uint32_t* Wt00 = Wtb;            uint32_t* Wt01 = Wtb + WBSZ;
    uint32_t* Wt10 = Wtb + 2*WBSZ;   uint32_t* Wt11 = Wtb + 3*WBSZ;
    uint32_t* UF00 = UFB;            uint32_t* UF01 = UFB + UFSZ;
    uint32_t* UF10 = UFB + 2*UFSZ;   uint32_t* UF11 = UFB + 3*UFSZ;

    build_wtb<<<(4 * GATES * (EMB/2) + 255) / 256, 256>>>(W, Wtb);
    build_ufragb<<<(4 * 64 * 4 * 32 * 4 + 255) / 256, 256>>>(U, UFB);

    dim3 gg(GATES / 128, MTOT / 128);   // (4, 800)
    dim3 lg(BATCH / 8, 2);              // (64, 2)

    gemm_bf<<<gg, 256, GSMEM>>>(x, Wt00, b00, zxf);
    gemm_bf<<<gg, 256, GSMEM>>>(x, Wt01, b01, zxb);
    lstm_tc<<<lg, 512>>>(zxf, zxb, UF00, UF01, s0f, s0b);

    gemm_bf<<<gg, 256, GSMEM>>>(s0f, Wt10, b10, zxf);
    gemm_bf<<<gg, 256, GSMEM>>>(s0b, Wt11, b11, zxb);
    lstm_tc<<<lg, 512>>>(zxf, zxb, UF10, UF11, s1f, s1b);

    int n4 = MTOT * HID / 4;
    combine<<<(n4 + 255) / 256, 256>>>(s1f, s0f, s1b, s0b, (float*)d_out, n4);
}